// round 7
// baseline (speedup 1.0000x reference)
#include <cuda_runtime.h>
#include <cuda_fp16.h>
#include <math.h>
#include <stdint.h>

// Problem dims (fixed)
#define BB 4
#define SS 2048
#define MD 1024
#define HD 1024
#define NT 8192   // BB*SS

// GEMM tiling: CTA 128x256, 8 warps (2x4) of 64x64, K-chunk 64
#define KC 64
// Stage: A hi(16K) + A lo(16K) + B hi(32K) = 64KB, 3 stages
#define OFF_AH 0
#define OFF_AL 16384
#define OFF_BH 32768
#define STAGE  65536
#define SMEMSZ (3 * STAGE)    // 192 KB

#define SWZ(o) ((o) ^ (((o) >> 3) & 0x70))

// ---------------------------------------------------------------------------
// Scratch (__device__ globals; allocation-free rule)
// ---------------------------------------------------------------------------
__device__ __align__(256) __half g_Xq_hi[(size_t)NT * MD];
__device__ __align__(256) __half g_Xq_lo[(size_t)NT * MD];
__device__ __align__(256) __half g_Xk_hi[(size_t)NT * MD];
__device__ __align__(256) __half g_Xk_lo[(size_t)NT * MD];
__device__ __align__(256) __half g_Xv_hi[(size_t)NT * MD];
__device__ __align__(256) __half g_Xv_lo[(size_t)NT * MD];
__device__ __align__(256) __half g_Wq_hi[(size_t)HD * MD];
__device__ __align__(256) __half g_Wk_hi[(size_t)HD * MD];
__device__ __align__(256) __half g_Wv_hi[(size_t)HD * MD];
__device__ __align__(256) __half g_QH_hi[(size_t)NT * HD];
__device__ __align__(256) __half g_QH_lo[(size_t)NT * HD];
__device__ __align__(256) __half g_KH_hi[(size_t)NT * HD];
__device__ __align__(256) __half g_VH_hi[(size_t)NT * HD];
__device__ __align__(256) __half g_VT_hi[(size_t)BB * HD * SS];
__device__ __align__(256) float  g_SC[(size_t)BB * SS * SS];
__device__ __align__(256) __half g_P_hi[(size_t)BB * SS * SS];
__device__ __align__(256) __half g_P_lo[(size_t)BB * SS * SS];

// ---------------------------------------------------------------------------
__device__ __forceinline__ uint32_t smem_u32(const void* p) {
    uint32_t a;
    asm("{ .reg .u64 t; cvta.to.shared.u64 t, %1; cvt.u32.u64 %0, t; }"
        : "=r"(a) : "l"(p));
    return a;
}
#define CP16(dst, src) asm volatile("cp.async.cg.shared.global [%0], [%1], 16;" :: "r"(dst), "l"(src))
#define CP_COMMIT()    asm volatile("cp.async.commit_group;" ::: "memory")
#define CP_WAIT1()     asm volatile("cp.async.wait_group 1;" ::: "memory")

__device__ __forceinline__ void ldsm4(uint32_t r[4], uint32_t a) {
    asm volatile("ldmatrix.sync.aligned.m8n8.x4.shared.b16 {%0,%1,%2,%3}, [%4];"
                 : "=r"(r[0]), "=r"(r[1]), "=r"(r[2]), "=r"(r[3]) : "r"(a));
}
// fp32-accumulate MMA (hi pass)
__device__ __forceinline__ void mma_f32(float d[4], const uint32_t a[4],
                                        uint32_t b0, uint32_t b1) {
    asm volatile(
        "mma.sync.aligned.m16n8k16.row.col.f32.f16.f16.f32 "
        "{%0,%1,%2,%3}, {%4,%5,%6,%7}, {%8,%9}, {%0,%1,%2,%3};"
        : "+f"(d[0]), "+f"(d[1]), "+f"(d[2]), "+f"(d[3])
        : "r"(a[0]), "r"(a[1]), "r"(a[2]), "r"(a[3]), "r"(b0), "r"(b1));
}
// fp16-accumulate MMA (lo pass; sums are ~2^-12 of hi, fp16 acc is safe)
__device__ __forceinline__ void mma_h16(uint32_t c[2], const uint32_t a[4],
                                        uint32_t b0, uint32_t b1) {
    asm volatile(
        "mma.sync.aligned.m16n8k16.row.col.f16.f16.f16.f16 "
        "{%0,%1}, {%2,%3,%4,%5}, {%6,%7}, {%0,%1};"
        : "+r"(c[0]), "+r"(c[1])
        : "r"(a[0]), "r"(a[1]), "r"(a[2]), "r"(a[3]), "r"(b0), "r"(b1));
}

__device__ __forceinline__ void split_h(float x, __half& h, __half& l) {
    h = __float2half_rn(x);
    l = __float2half_rn(x - __half2float(h));
}
__device__ __forceinline__ uint32_t pack_h2(__half a, __half b) {
    union { __half2 v; uint32_t u; } t;
    t.v.x = a; t.v.y = b;
    return t.u;
}
__device__ __forceinline__ float2 h2f2(uint32_t u) {
    union { uint32_t u; __half2 v; } t;
    t.u = u;
    return __half22float2(t.v);
}

// ---------------------------------------------------------------------------
// 2-pass fp16 mma.sync GEMM (NT): C = (Ah*Bh)_f32acc + (Al*Bh)_f16acc
// A: [M,K] hi/lo fp16 (lda). B: [N,K] hi fp16 (ldb).
// CTA 128x256, 8 warps (2x4) of 64x64, KC=64, 3-stage cp.async, 1 sync/chunk.
// MODE 0: out fp16 hi/lo + bias (Q proj)
// MODE 1: out fp16 hi + bias (K/V proj)
// MODE 2: out fp32 * alpha, causal tile skip 2*bn>bm (scores)
// MODE 3: out fp32, k-chunks limited to (bm+1)*2 (PV)
// ---------------------------------------------------------------------------
template <int MODE>
__global__ void __launch_bounds__(256, 1)
gemm2p(const __half* __restrict__ Ahi, const __half* __restrict__ Alo,
       const __half* __restrict__ Bhi,
       const float* __restrict__ bias,
       __half* __restrict__ Chi, __half* __restrict__ Clo,
       float* __restrict__ Cf,
       int lda, int ldb, int ldc, int nkt0, float alpha,
       size_t sA, size_t sB, size_t sC)
{
    const int bm = blockIdx.y, bn = blockIdx.x, bz = blockIdx.z;
    if (MODE == 2 && 2 * bn > bm) return;
    const int nkt = (MODE == 3) ? (bm + 1) * 2 : nkt0;

    extern __shared__ char smem[];
    const uint32_t sb = smem_u32(smem);
    const int tid = threadIdx.x, lane = tid & 31, wid = tid >> 5;
    const int wm = wid >> 2, wn = wid & 3;

    const char* gAh = (const char*)(Ahi + (size_t)bz * sA + (size_t)(bm * 128) * lda);
    const char* gAl = (const char*)(Alo + (size_t)bz * sA + (size_t)(bm * 128) * lda);
    const char* gBh = (const char*)(Bhi + (size_t)bz * sB + (size_t)(bn * 256) * ldb);
    const size_t ldaB = (size_t)lda * 2, ldbB = (size_t)ldb * 2;

    auto load_chunk = [&](int c, int buf) {
        const uint32_t st = sb + buf * STAGE;
        const size_t cb = (size_t)c * 128;
#pragma unroll
        for (int i = 0; i < 4; ++i) {          // A: 128 rows x 128B (hi+lo)
            const int idx = tid + i * 256;
            const int row = idx >> 3, seg = (idx & 7) * 16;
            const size_t go = (size_t)row * ldaB + cb + seg;
            const uint32_t so = SWZ(row * 128 + seg);
            CP16(st + OFF_AH + so, gAh + go);
            CP16(st + OFF_AL + so, gAl + go);
        }
#pragma unroll
        for (int i = 0; i < 8; ++i) {          // B: 256 rows x 128B (hi)
            const int idx = tid + i * 256;
            const int row = idx >> 3, seg = (idx & 7) * 16;
            const size_t go = (size_t)row * ldbB + cb + seg;
            const uint32_t so = SWZ(row * 128 + seg);
            CP16(st + OFF_BH + so, gBh + go);
        }
        CP_COMMIT();
    };

    float    acc[4][8][4];     // hi-pass fp32 accumulators
    uint32_t acl[4][8][2];     // lo-pass fp16 accumulators (packed half2)
#pragma unroll
    for (int mi = 0; mi < 4; ++mi)
#pragma unroll
        for (int nf = 0; nf < 8; ++nf) {
#pragma unroll
            for (int r = 0; r < 4; ++r) acc[mi][nf][r] = 0.f;
            acl[mi][nf][0] = 0u; acl[mi][nf][1] = 0u;
        }

    const int lrow = lane & 15;
    const int lcb0 = (lane >> 4) * 16;
    const int arow = wm * 64 + lrow;
    const int brow = wn * 64 + lrow;

    load_chunk(0, 0);
    load_chunk(1, 1);

    for (int c = 0; c < nkt; ++c) {
        CP_WAIT1();
        __syncthreads();
        if (c + 2 < nkt) load_chunk(c + 2, (c + 2) % 3);
        else             CP_COMMIT();   // empty group keeps wait count aligned

        const uint32_t st = sb + (c % 3) * STAGE;
#pragma unroll
        for (int kk = 0; kk < 4; ++kk) {
            const int cb = kk * 32 + lcb0;
            uint32_t a[4][4], bh[4][4];
#pragma unroll
            for (int mi = 0; mi < 4; ++mi)
                ldsm4(a[mi], st + OFF_AH + SWZ((arow + mi * 16) * 128 + cb));
#pragma unroll
            for (int nj = 0; nj < 4; ++nj)
                ldsm4(bh[nj], st + OFF_BH + SWZ((brow + nj * 16) * 128 + cb));
            // hi pass: fp32 accumulate
#pragma unroll
            for (int mi = 0; mi < 4; ++mi)
#pragma unroll
                for (int nj = 0; nj < 4; ++nj) {
                    mma_f32(acc[mi][nj * 2 + 0], a[mi], bh[nj][0], bh[nj][2]);
                    mma_f32(acc[mi][nj * 2 + 1], a[mi], bh[nj][1], bh[nj][3]);
                }
            // lo pass: reload A regs with lo parts, fp16 accumulate
#pragma unroll
            for (int mi = 0; mi < 4; ++mi)
                ldsm4(a[mi], st + OFF_AL + SWZ((arow + mi * 16) * 128 + cb));
#pragma unroll
            for (int mi = 0; mi < 4; ++mi)
#pragma unroll
                for (int nj = 0; nj < 4; ++nj) {
                    mma_h16(acl[mi][nj * 2 + 0], a[mi], bh[nj][0], bh[nj][2]);
                    mma_h16(acl[mi][nj * 2 + 1], a[mi], bh[nj][1], bh[nj][3]);
                }
        }
    }

    // ---- epilogue: d = acc_f32 + float(acc_f16) ----
    const int lr = lane >> 2;
    const int lc = (lane & 3) * 2;
#pragma unroll
    for (int mi = 0; mi < 4; ++mi) {
        const int row0 = bm * 128 + wm * 64 + mi * 16 + lr;
#pragma unroll
        for (int nf = 0; nf < 8; ++nf) {
            const int col = bn * 256 + wn * 64 + nf * 8 + lc;
            float* d = acc[mi][nf];
            const float2 lo01 = h2f2(acl[mi][nf][0]);
            const float2 lo23 = h2f2(acl[mi][nf][1]);
            d[0] += lo01.x; d[1] += lo01.y;
            d[2] += lo23.x; d[3] += lo23.y;
            if (MODE == 0) {
                const float b0 = bias[col], b1 = bias[col + 1];
                __half h0, l0, h1, l1;
                split_h(d[0] + b0, h0, l0); split_h(d[1] + b1, h1, l1);
                *(uint32_t*)(Chi + (size_t)row0 * ldc + col) = pack_h2(h0, h1);
                *(uint32_t*)(Clo + (size_t)row0 * ldc + col) = pack_h2(l0, l1);
                split_h(d[2] + b0, h0, l0); split_h(d[3] + b1, h1, l1);
                *(uint32_t*)(Chi + (size_t)(row0 + 8) * ldc + col) = pack_h2(h0, h1);
                *(uint32_t*)(Clo + (size_t)(row0 + 8) * ldc + col) = pack_h2(l0, l1);
            } else if (MODE == 1) {
                const float b0 = bias[col], b1 = bias[col + 1];
                *(uint32_t*)(Chi + (size_t)row0 * ldc + col) =
                    pack_h2(__float2half_rn(d[0] + b0), __float2half_rn(d[1] + b1));
                *(uint32_t*)(Chi + (size_t)(row0 + 8) * ldc + col) =
                    pack_h2(__float2half_rn(d[2] + b0), __float2half_rn(d[3] + b1));
            } else {
                float* cp = Cf + (size_t)bz * sC;
                float2 o0 = { d[0] * alpha, d[1] * alpha };
                float2 o1 = { d[2] * alpha, d[3] * alpha };
                *(float2*)(cp + (size_t)row0 * ldc + col) = o0;
                *(float2*)(cp + (size_t)(row0 + 8) * ldc + col) = o1;
            }
        }
    }
}

// ---------------------------------------------------------------------------
// fp32 -> fp16 hi/lo split (dual) and hi-only
// ---------------------------------------------------------------------------
__global__ void __launch_bounds__(256)
convert_split_h(const float* __restrict__ src, __half* __restrict__ hi,
                __half* __restrict__ lo, size_t n4)
{
    size_t i = (size_t)blockIdx.x * blockDim.x + threadIdx.x;
    if (i >= n4) return;
    float4 x = ((const float4*)src)[i];
    union { __half h[4]; uint2 u; } H, L;
    split_h(x.x, H.h[0], L.h[0]);
    split_h(x.y, H.h[1], L.h[1]);
    split_h(x.z, H.h[2], L.h[2]);
    split_h(x.w, H.h[3], L.h[3]);
    ((uint2*)hi)[i] = H.u;
    ((uint2*)lo)[i] = L.u;
}

__global__ void __launch_bounds__(256)
convert_hi(const float* __restrict__ src, __half* __restrict__ hi, size_t n4)
{
    size_t i = (size_t)blockIdx.x * blockDim.x + threadIdx.x;
    if (i >= n4) return;
    float4 x = ((const float4*)src)[i];
    union { __half h[4]; uint2 u; } H;
    H.h[0] = __float2half_rn(x.x);
    H.h[1] = __float2half_rn(x.y);
    H.h[2] = __float2half_rn(x.z);
    H.h[3] = __float2half_rn(x.w);
    ((uint2*)hi)[i] = H.u;
}

// ---------------------------------------------------------------------------
// fp16 transpose per batch: src [B*S, H] -> dst [B][H][S]
// ---------------------------------------------------------------------------
__global__ void __launch_bounds__(256)
transpose_h(const __half* __restrict__ src, __half* __restrict__ dst)
{
    __shared__ __half t[32][33];
    const int b = blockIdx.z;
    const int h0 = blockIdx.x * 32, s0 = blockIdx.y * 32;
    const int tx = threadIdx.x, ty = threadIdx.y;  // 32 x 8
#pragma unroll
    for (int i = 0; i < 4; ++i)
        t[ty + i * 8][tx] = src[((size_t)b * SS + s0 + ty + i * 8) * HD + h0 + tx];
    __syncthreads();
#pragma unroll
    for (int i = 0; i < 4; ++i)
        dst[((size_t)b * HD + h0 + ty + i * 8) * SS + s0 + tx] = t[tx][ty + i * 8];
}

// ---------------------------------------------------------------------------
// Masked causal softmax: SC fp32 -> P hi/lo fp16, zero-filled to 128-boundary.
// ---------------------------------------------------------------------------
__global__ void __launch_bounds__(256)
softmax_rows(const int* __restrict__ mask, const float* __restrict__ SC,
             __half* __restrict__ Phi, __half* __restrict__ Plo)
{
    const int b = blockIdx.y;
    const int i = blockIdx.x;
    const size_t rowoff = ((size_t)b * SS + i) * SS;
    const float* row = SC + rowoff;
    const int* mrow = mask + (size_t)b * SS;
    const int tid = threadIdx.x;
    const int nvalid = i + 1;
    const int nfill = ((i >> 7) + 1) << 7;

    float vals[8];
    float vmax = -INFINITY;
#pragma unroll
    for (int t = 0; t < 8; ++t) {
        int j = tid + t * 256;
        float s = -INFINITY;
        if (j < nvalid) {
            s = row[j];
            if (mrow[j] == 0) s = -1e9f;
        }
        vals[t] = s;
        vmax = fmaxf(vmax, s);
    }

    __shared__ float red[8];
#pragma unroll
    for (int o = 16; o; o >>= 1) vmax = fmaxf(vmax, __shfl_xor_sync(~0u, vmax, o));
    if ((tid & 31) == 0) red[tid >> 5] = vmax;
    __syncthreads();
    if (tid < 32) {
        float x = (tid < 8) ? red[tid] : -INFINITY;
#pragma unroll
        for (int o = 4; o; o >>= 1) x = fmaxf(x, __shfl_xor_sync(~0u, x, o));
        if (tid == 0) red[0] = x;
    }
    __syncthreads();
    vmax = red[0];
    __syncthreads();

    float lsum = 0.f;
#pragma unroll
    for (int t = 0; t < 8; ++t) {
        float e = __expf(vals[t] - vmax);
        vals[t] = e;
        lsum += e;
    }
#pragma unroll
    for (int o = 16; o; o >>= 1) lsum += __shfl_xor_sync(~0u, lsum, o);
    if ((tid & 31) == 0) red[tid >> 5] = lsum;
    __syncthreads();
    if (tid < 32) {
        float x = (tid < 8) ? red[tid] : 0.f;
#pragma unroll
        for (int o = 4; o; o >>= 1) x += __shfl_xor_sync(~0u, x, o);
        if (tid == 0) red[0] = x;
    }
    __syncthreads();
    const float rinv = 1.0f / red[0];

#pragma unroll
    for (int t = 0; t < 8; ++t) {
        int j = tid + t * 256;
        if (j < nfill) {
            float p = vals[t] * rinv;  // 0 for j > i
            __half H, L;
            split_h(p, H, L);
            Phi[rowoff + j] = H;
            Plo[rowoff + j] = L;
        }
    }
}

// ---------------------------------------------------------------------------
extern "C" void kernel_launch(void* const* d_in, const int* in_sizes, int n_in,
                              void* d_out, int out_size)
{
    (void)in_sizes; (void)n_in; (void)out_size;

    const float* q    = (const float*)d_in[0];
    const float* k    = (const float*)d_in[1];
    const float* v    = (const float*)d_in[2];
    const int*   mask = (const int*)  d_in[3];
    const float* Wq   = (const float*)d_in[4];
    const float* bq   = (const float*)d_in[5];
    const float* Wk   = (const float*)d_in[6];
    const float* bk   = (const float*)d_in[7];
    const float* Wv   = (const float*)d_in[8];
    const float* bv   = (const float*)d_in[9];
    float* out = (float*)d_out;

    static bool init = false;
    static __half *Xqh, *Xql, *Xkh, *Xkl, *Xvh, *Xvl;
    static __half *Wqh, *Wkh, *Wvh;
    static __half *QHh, *QHl, *KHh, *VHh, *VTh, *Ph, *Pl;
    static float *SC;
    if (!init) {
        void* p;
        cudaGetSymbolAddress(&p, g_Xq_hi); Xqh = (__half*)p;
        cudaGetSymbolAddress(&p, g_Xq_lo); Xql = (__half*)p;
        cudaGetSymbolAddress(&p, g_Xk_hi); Xkh = (__half*)p;
        cudaGetSymbolAddress(&p, g_Xk_lo); Xkl = (__half*)p;
        cudaGetSymbolAddress(&p, g_Xv_hi); Xvh = (__half*)p;
        cudaGetSymbolAddress(&p, g_Xv_lo); Xvl = (__half*)p;
        cudaGetSymbolAddress(&p, g_Wq_hi); Wqh = (__half*)p;
        cudaGetSymbolAddress(&p, g_Wk_hi); Wkh = (__half*)p;
        cudaGetSymbolAddress(&p, g_Wv_hi); Wvh = (__half*)p;
        cudaGetSymbolAddress(&p, g_QH_hi); QHh = (__half*)p;
        cudaGetSymbolAddress(&p, g_QH_lo); QHl = (__half*)p;
        cudaGetSymbolAddress(&p, g_KH_hi); KHh = (__half*)p;
        cudaGetSymbolAddress(&p, g_VH_hi); VHh = (__half*)p;
        cudaGetSymbolAddress(&p, g_VT_hi); VTh = (__half*)p;
        cudaGetSymbolAddress(&p, g_P_hi);  Ph  = (__half*)p;
        cudaGetSymbolAddress(&p, g_P_lo);  Pl  = (__half*)p;
        cudaGetSymbolAddress(&p, g_SC);    SC  = (float*)p;
        cudaFuncSetAttribute((const void*)gemm2p<0>, cudaFuncAttributeMaxDynamicSharedMemorySize, SMEMSZ);
        cudaFuncSetAttribute((const void*)gemm2p<1>, cudaFuncAttributeMaxDynamicSharedMemorySize, SMEMSZ);
        cudaFuncSetAttribute((const void*)gemm2p<2>, cudaFuncAttributeMaxDynamicSharedMemorySize, SMEMSZ);
        cudaFuncSetAttribute((const void*)gemm2p<3>, cudaFuncAttributeMaxDynamicSharedMemorySize, SMEMSZ);
        init = true;
    }

    // 1) Convert inputs: X dual fp16, W hi only
    const size_t nX4 = (size_t)NT * MD / 4;
    const size_t nW4 = (size_t)HD * MD / 4;
    convert_split_h<<<(unsigned)((nX4 + 255) / 256), 256>>>(q, Xqh, Xql, nX4);
    convert_split_h<<<(unsigned)((nX4 + 255) / 256), 256>>>(k, Xkh, Xkl, nX4);
    convert_split_h<<<(unsigned)((nX4 + 255) / 256), 256>>>(v, Xvh, Xvl, nX4);
    convert_hi<<<(unsigned)((nW4 + 255) / 256), 256>>>(Wq, Wqh, nW4);
    convert_hi<<<(unsigned)((nW4 + 255) / 256), 256>>>(Wk, Wkh, nW4);
    convert_hi<<<(unsigned)((nW4 + 255) / 256), 256>>>(Wv, Wvh, nW4);

    // 2) Projections: Q -> dual out, K/V -> hi out
    dim3 gproj(HD / 256, NT / 128, 1);
    gemm2p<0><<<gproj, 256, SMEMSZ>>>(Xqh, Xql, Wqh, bq, QHh, QHl, nullptr,
                                      MD, MD, HD, MD / KC, 1.f, 0, 0, 0);
    gemm2p<1><<<gproj, 256, SMEMSZ>>>(Xkh, Xkl, Wkh, bk, KHh, nullptr, nullptr,
                                      MD, MD, HD, MD / KC, 1.f, 0, 0, 0);
    gemm2p<1><<<gproj, 256, SMEMSZ>>>(Xvh, Xvl, Wvh, bv, VHh, nullptr, nullptr,
                                      MD, MD, HD, MD / KC, 1.f, 0, 0, 0);

    // 3) Transpose V (hi) to [B][H][S]
    dim3 gt(HD / 32, SS / 32, BB);
    transpose_h<<<gt, dim3(32, 8)>>>(VHh, VTh);

    // 4) Scores (2-pass, causal skip), alpha = 1/sqrt(1024)
    dim3 gsc(SS / 256, SS / 128, BB);
    gemm2p<2><<<gsc, 256, SMEMSZ>>>(QHh, QHl, KHh, nullptr, nullptr, nullptr, SC,
                                    HD, HD, SS, HD / KC, 1.0f / 32.0f,
                                    (size_t)SS * HD, (size_t)SS * HD, (size_t)SS * SS);

    // 5) Softmax + fp16 hi/lo split of P
    softmax_rows<<<dim3(SS, BB), 256>>>(mask, SC, Ph, Pl);

    // 6) OUT = P @ VT^T (2-pass NT; k-chunks limited by causality)
    dim3 go(HD / 256, SS / 128, BB);
    gemm2p<3><<<go, 256, SMEMSZ>>>(Ph, Pl, VTh, nullptr, nullptr, nullptr, out,
                                   SS, SS, HD, 0, 1.f,
                                   (size_t)SS * SS, (size_t)HD * SS, (size_t)SS * HD);
}

// round 8
// speedup vs baseline: 1.3708x; 1.3708x over previous
#include <cuda_runtime.h>
#include <cuda_fp16.h>
#include <math.h>
#include <stdint.h>

// Problem dims (fixed)
#define BB 4
#define SS 2048
#define MD 1024
#define HD 1024
#define NT 8192   // BB*SS

// GEMM tiling: CTA 128x256, 16 warps (2x8) of 64x32, K-chunk 64
#define KC 64
#define SMEMSZ 196608   // 3x64KB (2-pass) or 4x48KB (1-pass)

#define SWZ(o) ((o) ^ (((o) >> 3) & 0x70))

// ---------------------------------------------------------------------------
// Scratch (__device__ globals; allocation-free rule)
// ---------------------------------------------------------------------------
__device__ __align__(256) __half g_Xq_hi[(size_t)NT * MD];
__device__ __align__(256) __half g_Xq_lo[(size_t)NT * MD];
__device__ __align__(256) __half g_Xk_hi[(size_t)NT * MD];
__device__ __align__(256) __half g_Xk_lo[(size_t)NT * MD];
__device__ __align__(256) __half g_Xv_hi[(size_t)NT * MD];
__device__ __align__(256) __half g_Xv_lo[(size_t)NT * MD];
__device__ __align__(256) __half g_Wq_hi[(size_t)HD * MD];
__device__ __align__(256) __half g_Wk_hi[(size_t)HD * MD];
__device__ __align__(256) __half g_Wv_hi[(size_t)HD * MD];
__device__ __align__(256) __half g_QH_hi[(size_t)NT * HD];
__device__ __align__(256) __half g_KH_hi[(size_t)NT * HD];
__device__ __align__(256) __half g_VH_hi[(size_t)NT * HD];
__device__ __align__(256) __half g_VT_hi[(size_t)BB * HD * SS];
__device__ __align__(256) float  g_SC[(size_t)BB * SS * SS];
__device__ __align__(256) __half g_P_hi[(size_t)BB * SS * SS];

// ---------------------------------------------------------------------------
__device__ __forceinline__ uint32_t smem_u32(const void* p) {
    uint32_t a;
    asm("{ .reg .u64 t; cvta.to.shared.u64 t, %1; cvt.u32.u64 %0, t; }"
        : "=r"(a) : "l"(p));
    return a;
}
#define CP16(dst, src) asm volatile("cp.async.cg.shared.global [%0], [%1], 16;" :: "r"(dst), "l"(src))
#define CP_COMMIT()    asm volatile("cp.async.commit_group;" ::: "memory")

__device__ __forceinline__ void ldsm4(uint32_t r[4], uint32_t a) {
    asm volatile("ldmatrix.sync.aligned.m8n8.x4.shared.b16 {%0,%1,%2,%3}, [%4];"
                 : "=r"(r[0]), "=r"(r[1]), "=r"(r[2]), "=r"(r[3]) : "r"(a));
}
__device__ __forceinline__ void mma_f32(float d[4], const uint32_t a[4],
                                        uint32_t b0, uint32_t b1) {
    asm volatile(
        "mma.sync.aligned.m16n8k16.row.col.f32.f16.f16.f32 "
        "{%0,%1,%2,%3}, {%4,%5,%6,%7}, {%8,%9}, {%0,%1,%2,%3};"
        : "+f"(d[0]), "+f"(d[1]), "+f"(d[2]), "+f"(d[3])
        : "r"(a[0]), "r"(a[1]), "r"(a[2]), "r"(a[3]), "r"(b0), "r"(b1));
}

__device__ __forceinline__ void split_h(float x, __half& h, __half& l) {
    h = __float2half_rn(x);
    l = __float2half_rn(x - __half2float(h));
}
__device__ __forceinline__ uint32_t pack_h2(__half a, __half b) {
    union { __half2 v; uint32_t u; } t;
    t.v.x = a; t.v.y = b;
    return t.u;
}

// ---------------------------------------------------------------------------
// fp16 mma.sync GEMM (NT), PASSES = 1 or 2 A-operand passes.
// C = (Ah [+ Al]) * Bh^T [+ bias] [* alpha]
// CTA 128x256, 16 warps (2x8) of 64x32, KC=64.
// PASSES==2: 3-stage (64KB) pipeline; PASSES==1: 4-stage (48KB).
// MODE 1: out fp16 hi + bias (projections)
// MODE 2: out fp32 * alpha, causal tile skip 2*bn>bm (scores)
// MODE 3: out fp32, k-chunks limited to (bm+1)*2 (PV)
// ---------------------------------------------------------------------------
template <int MODE, int PASSES>
__global__ void __launch_bounds__(512, 1)
gemmX(const __half* __restrict__ Ahi, const __half* __restrict__ Alo,
      const __half* __restrict__ Bhi,
      const float* __restrict__ bias,
      __half* __restrict__ Ch, float* __restrict__ Cf,
      int lda, int ldb, int ldc, int nkt0, float alpha,
      size_t sA, size_t sB, size_t sC)
{
    constexpr int NS   = (PASSES == 2) ? 3 : 4;
    constexpr int STG  = (PASSES == 2) ? 65536 : 49152;
    constexpr int OFFA = 0;
    constexpr int OFFL = 16384;
    constexpr int OFFB = (PASSES == 2) ? 32768 : 16384;

    const int bm = blockIdx.y, bn = blockIdx.x, bz = blockIdx.z;
    if (MODE == 2 && 2 * bn > bm) return;
    const int nkt = (MODE == 3) ? (bm + 1) * 2 : nkt0;

    extern __shared__ char smem[];
    const uint32_t sb = smem_u32(smem);
    const int tid = threadIdx.x, lane = tid & 31, wid = tid >> 5;
    const int wm = wid >> 3, wn = wid & 7;

    const char* gAh = (const char*)(Ahi + (size_t)bz * sA + (size_t)(bm * 128) * lda);
    const char* gAl = (const char*)(Alo + (size_t)bz * sA + (size_t)(bm * 128) * lda);
    const char* gBh = (const char*)(Bhi + (size_t)bz * sB + (size_t)(bn * 256) * ldb);
    const size_t ldaB = (size_t)lda * 2, ldbB = (size_t)ldb * 2;

    auto load_chunk = [&](int c, int buf) {
        const uint32_t st = sb + buf * STG;
        const size_t cb = (size_t)c * 128;
#pragma unroll
        for (int i = 0; i < 2; ++i) {          // A: 128 rows x 128B
            const int idx = tid + i * 512;
            const int row = idx >> 3, seg = (idx & 7) * 16;
            const size_t go = (size_t)row * ldaB + cb + seg;
            const uint32_t so = SWZ(row * 128 + seg);
            CP16(st + OFFA + so, gAh + go);
            if (PASSES == 2) CP16(st + OFFL + so, gAl + go);
        }
#pragma unroll
        for (int i = 0; i < 4; ++i) {          // B: 256 rows x 128B
            const int idx = tid + i * 512;
            const int row = idx >> 3, seg = (idx & 7) * 16;
            const size_t go = (size_t)row * ldbB + cb + seg;
            const uint32_t so = SWZ(row * 128 + seg);
            CP16(st + OFFB + so, gBh + go);
        }
        CP_COMMIT();
    };

    float acc[4][4][4];
#pragma unroll
    for (int mi = 0; mi < 4; ++mi)
#pragma unroll
        for (int nf = 0; nf < 4; ++nf)
#pragma unroll
            for (int r = 0; r < 4; ++r) acc[mi][nf][r] = 0.f;

    const int lrow = lane & 15;
    const int lcb0 = (lane >> 4) * 16;
    const int arow = wm * 64 + lrow;
    const int brow = wn * 32 + lrow;

#pragma unroll
    for (int i = 0; i < NS - 1; ++i)
        if (i < nkt) load_chunk(i, i);
        else         CP_COMMIT();

    for (int c = 0; c < nkt; ++c) {
        if (PASSES == 2) asm volatile("cp.async.wait_group 1;" ::: "memory");
        else             asm volatile("cp.async.wait_group 2;" ::: "memory");
        __syncthreads();
        if (c + NS - 1 < nkt) load_chunk(c + NS - 1, (c + NS - 1) % NS);
        else                  CP_COMMIT();   // keep wait-group count aligned

        const uint32_t st = sb + (c % NS) * STG;
#pragma unroll
        for (int kk = 0; kk < 4; ++kk) {
            const int cb = kk * 32 + lcb0;
            uint32_t a[4][4], bh[2][4];
#pragma unroll
            for (int mi = 0; mi < 4; ++mi)
                ldsm4(a[mi], st + OFFA + SWZ((arow + mi * 16) * 128 + cb));
#pragma unroll
            for (int nj = 0; nj < 2; ++nj)
                ldsm4(bh[nj], st + OFFB + SWZ((brow + nj * 16) * 128 + cb));
#pragma unroll
            for (int mi = 0; mi < 4; ++mi)
#pragma unroll
                for (int nj = 0; nj < 2; ++nj) {
                    mma_f32(acc[mi][nj * 2 + 0], a[mi], bh[nj][0], bh[nj][2]);
                    mma_f32(acc[mi][nj * 2 + 1], a[mi], bh[nj][1], bh[nj][3]);
                }
            if (PASSES == 2) {
#pragma unroll
                for (int mi = 0; mi < 4; ++mi)
                    ldsm4(a[mi], st + OFFL + SWZ((arow + mi * 16) * 128 + cb));
#pragma unroll
                for (int mi = 0; mi < 4; ++mi)
#pragma unroll
                    for (int nj = 0; nj < 2; ++nj) {
                        mma_f32(acc[mi][nj * 2 + 0], a[mi], bh[nj][0], bh[nj][2]);
                        mma_f32(acc[mi][nj * 2 + 1], a[mi], bh[nj][1], bh[nj][3]);
                    }
            }
        }
    }

    // ---- epilogue ----
    const int lr = lane >> 2;
    const int lc = (lane & 3) * 2;
#pragma unroll
    for (int mi = 0; mi < 4; ++mi) {
        const int row0 = bm * 128 + wm * 64 + mi * 16 + lr;
#pragma unroll
        for (int nf = 0; nf < 4; ++nf) {
            const int col = bn * 256 + wn * 32 + nf * 8 + lc;
            float* d = acc[mi][nf];
            if (MODE == 1) {
                const float b0 = bias[col], b1 = bias[col + 1];
                *(uint32_t*)(Ch + (size_t)row0 * ldc + col) =
                    pack_h2(__float2half_rn(d[0] + b0), __float2half_rn(d[1] + b1));
                *(uint32_t*)(Ch + (size_t)(row0 + 8) * ldc + col) =
                    pack_h2(__float2half_rn(d[2] + b0), __float2half_rn(d[3] + b1));
            } else {
                float* cp = Cf + (size_t)bz * sC;
                float2 o0 = { d[0] * alpha, d[1] * alpha };
                float2 o1 = { d[2] * alpha, d[3] * alpha };
                *(float2*)(cp + (size_t)row0 * ldc + col) = o0;
                *(float2*)(cp + (size_t)(row0 + 8) * ldc + col) = o1;
            }
        }
    }
}

// ---------------------------------------------------------------------------
// Fused converts: 3 tensors in one launch (select by blockIdx.y)
// ---------------------------------------------------------------------------
__global__ void __launch_bounds__(256)
convert_split3(const float* __restrict__ s0, const float* __restrict__ s1,
               const float* __restrict__ s2,
               __half* __restrict__ h0, __half* __restrict__ h1, __half* __restrict__ h2,
               __half* __restrict__ l0, __half* __restrict__ l1, __half* __restrict__ l2,
               size_t n4)
{
    size_t i = (size_t)blockIdx.x * blockDim.x + threadIdx.x;
    if (i >= n4) return;
    const int t = blockIdx.y;
    const float* src = (t == 0) ? s0 : (t == 1) ? s1 : s2;
    __half* hi = (t == 0) ? h0 : (t == 1) ? h1 : h2;
    __half* lo = (t == 0) ? l0 : (t == 1) ? l1 : l2;
    float4 x = ((const float4*)src)[i];
    union { __half h[4]; uint2 u; } H, L;
    split_h(x.x, H.h[0], L.h[0]);
    split_h(x.y, H.h[1], L.h[1]);
    split_h(x.z, H.h[2], L.h[2]);
    split_h(x.w, H.h[3], L.h[3]);
    ((uint2*)hi)[i] = H.u;
    ((uint2*)lo)[i] = L.u;
}

__global__ void __launch_bounds__(256)
convert_hi3(const float* __restrict__ s0, const float* __restrict__ s1,
            const float* __restrict__ s2,
            __half* __restrict__ h0, __half* __restrict__ h1, __half* __restrict__ h2,
            size_t n4)
{
    size_t i = (size_t)blockIdx.x * blockDim.x + threadIdx.x;
    if (i >= n4) return;
    const int t = blockIdx.y;
    const float* src = (t == 0) ? s0 : (t == 1) ? s1 : s2;
    __half* hi = (t == 0) ? h0 : (t == 1) ? h1 : h2;
    float4 x = ((const float4*)src)[i];
    union { __half h[4]; uint2 u; } H;
    H.h[0] = __float2half_rn(x.x);
    H.h[1] = __float2half_rn(x.y);
    H.h[2] = __float2half_rn(x.z);
    H.h[3] = __float2half_rn(x.w);
    ((uint2*)hi)[i] = H.u;
}

// ---------------------------------------------------------------------------
// fp16 transpose per batch: src [B*S, H] -> dst [B][H][S]
// ---------------------------------------------------------------------------
__global__ void __launch_bounds__(256)
transpose_h(const __half* __restrict__ src, __half* __restrict__ dst)
{
    __shared__ __half t[32][33];
    const int b = blockIdx.z;
    const int h0 = blockIdx.x * 32, s0 = blockIdx.y * 32;
    const int tx = threadIdx.x, ty = threadIdx.y;  // 32 x 8
#pragma unroll
    for (int i = 0; i < 4; ++i)
        t[ty + i * 8][tx] = src[((size_t)b * SS + s0 + ty + i * 8) * HD + h0 + tx];
    __syncthreads();
#pragma unroll
    for (int i = 0; i < 4; ++i)
        dst[((size_t)b * HD + h0 + ty + i * 8) * SS + s0 + tx] = t[tx][ty + i * 8];
}

// ---------------------------------------------------------------------------
// Masked causal softmax: SC fp32 -> P hi fp16, zero-filled to 128-boundary.
// ---------------------------------------------------------------------------
__global__ void __launch_bounds__(256)
softmax_rows(const int* __restrict__ mask, const float* __restrict__ SC,
             __half* __restrict__ Phi)
{
    const int b = blockIdx.y;
    const int i = blockIdx.x;
    const size_t rowoff = ((size_t)b * SS + i) * SS;
    const float* row = SC + rowoff;
    const int* mrow = mask + (size_t)b * SS;
    const int tid = threadIdx.x;
    const int nvalid = i + 1;
    const int nfill = ((i >> 7) + 1) << 7;

    float vals[8];
    float vmax = -INFINITY;
#pragma unroll
    for (int t = 0; t < 8; ++t) {
        int j = tid + t * 256;
        float s = -INFINITY;
        if (j < nvalid) {
            s = row[j];
            if (mrow[j] == 0) s = -1e9f;
        }
        vals[t] = s;
        vmax = fmaxf(vmax, s);
    }

    __shared__ float red[8];
#pragma unroll
    for (int o = 16; o; o >>= 1) vmax = fmaxf(vmax, __shfl_xor_sync(~0u, vmax, o));
    if ((tid & 31) == 0) red[tid >> 5] = vmax;
    __syncthreads();
    if (tid < 32) {
        float x = (tid < 8) ? red[tid] : -INFINITY;
#pragma unroll
        for (int o = 4; o; o >>= 1) x = fmaxf(x, __shfl_xor_sync(~0u, x, o));
        if (tid == 0) red[0] = x;
    }
    __syncthreads();
    vmax = red[0];
    __syncthreads();

    float lsum = 0.f;
#pragma unroll
    for (int t = 0; t < 8; ++t) {
        float e = __expf(vals[t] - vmax);
        vals[t] = e;
        lsum += e;
    }
#pragma unroll
    for (int o = 16; o; o >>= 1) lsum += __shfl_xor_sync(~0u, lsum, o);
    if ((tid & 31) == 0) red[tid >> 5] = lsum;
    __syncthreads();
    if (tid < 32) {
        float x = (tid < 8) ? red[tid] : 0.f;
#pragma unroll
        for (int o = 4; o; o >>= 1) x += __shfl_xor_sync(~0u, x, o);
        if (tid == 0) red[0] = x;
    }
    __syncthreads();
    const float rinv = 1.0f / red[0];

#pragma unroll
    for (int t = 0; t < 8; ++t) {
        int j = tid + t * 256;
        if (j < nfill)
            Phi[rowoff + j] = __float2half_rn(vals[t] * rinv);  // 0 for j > i
    }
}

// ---------------------------------------------------------------------------
extern "C" void kernel_launch(void* const* d_in, const int* in_sizes, int n_in,
                              void* d_out, int out_size)
{
    (void)in_sizes; (void)n_in; (void)out_size;

    const float* q    = (const float*)d_in[0];
    const float* k    = (const float*)d_in[1];
    const float* v    = (const float*)d_in[2];
    const int*   mask = (const int*)  d_in[3];
    const float* Wq   = (const float*)d_in[4];
    const float* bq   = (const float*)d_in[5];
    const float* Wk   = (const float*)d_in[6];
    const float* bk   = (const float*)d_in[7];
    const float* Wv   = (const float*)d_in[8];
    const float* bv   = (const float*)d_in[9];
    float* out = (float*)d_out;

    static bool init = false;
    static __half *Xqh, *Xql, *Xkh, *Xkl, *Xvh, *Xvl;
    static __half *Wqh, *Wkh, *Wvh;
    static __half *QHh, *KHh, *VHh, *VTh, *Ph;
    static float *SC;
    if (!init) {
        void* p;
        cudaGetSymbolAddress(&p, g_Xq_hi); Xqh = (__half*)p;
        cudaGetSymbolAddress(&p, g_Xq_lo); Xql = (__half*)p;
        cudaGetSymbolAddress(&p, g_Xk_hi); Xkh = (__half*)p;
        cudaGetSymbolAddress(&p, g_Xk_lo); Xkl = (__half*)p;
        cudaGetSymbolAddress(&p, g_Xv_hi); Xvh = (__half*)p;
        cudaGetSymbolAddress(&p, g_Xv_lo); Xvl = (__half*)p;
        cudaGetSymbolAddress(&p, g_Wq_hi); Wqh = (__half*)p;
        cudaGetSymbolAddress(&p, g_Wk_hi); Wkh = (__half*)p;
        cudaGetSymbolAddress(&p, g_Wv_hi); Wvh = (__half*)p;
        cudaGetSymbolAddress(&p, g_QH_hi); QHh = (__half*)p;
        cudaGetSymbolAddress(&p, g_KH_hi); KHh = (__half*)p;
        cudaGetSymbolAddress(&p, g_VH_hi); VHh = (__half*)p;
        cudaGetSymbolAddress(&p, g_VT_hi); VTh = (__half*)p;
        cudaGetSymbolAddress(&p, g_P_hi);  Ph  = (__half*)p;
        cudaGetSymbolAddress(&p, g_SC);    SC  = (float*)p;
        cudaFuncSetAttribute((const void*)gemmX<1, 2>, cudaFuncAttributeMaxDynamicSharedMemorySize, SMEMSZ);
        cudaFuncSetAttribute((const void*)gemmX<2, 1>, cudaFuncAttributeMaxDynamicSharedMemorySize, SMEMSZ);
        cudaFuncSetAttribute((const void*)gemmX<3, 1>, cudaFuncAttributeMaxDynamicSharedMemorySize, SMEMSZ);
        init = true;
    }

    // 1) Converts (2 launches): X dual fp16, W hi-only
    const size_t nX4 = (size_t)NT * MD / 4;
    const size_t nW4 = (size_t)HD * MD / 4;
    convert_split3<<<dim3((unsigned)((nX4 + 255) / 256), 3), 256>>>(
        q, k, v, Xqh, Xkh, Xvh, Xql, Xkl, Xvl, nX4);
    convert_hi3<<<dim3((unsigned)((nW4 + 255) / 256), 3), 256>>>(
        Wq, Wk, Wv, Wqh, Wkh, Wvh, nW4);

    // 2) Projections (2-pass, hi out)
    dim3 gproj(HD / 256, NT / 128, 1);
    gemmX<1, 2><<<gproj, 512, SMEMSZ>>>(Xqh, Xql, Wqh, bq, QHh, nullptr,
                                        MD, MD, HD, MD / KC, 1.f, 0, 0, 0);
    gemmX<1, 2><<<gproj, 512, SMEMSZ>>>(Xkh, Xkl, Wkh, bk, KHh, nullptr,
                                        MD, MD, HD, MD / KC, 1.f, 0, 0, 0);
    gemmX<1, 2><<<gproj, 512, SMEMSZ>>>(Xvh, Xvl, Wvh, bv, VHh, nullptr,
                                        MD, MD, HD, MD / KC, 1.f, 0, 0, 0);

    // 3) Scores (1-pass, causal skip) — 6th launch: ncu -s 5 captures this
    dim3 gsc(SS / 256, SS / 128, BB);
    gemmX<2, 1><<<gsc, 512, SMEMSZ>>>(QHh, nullptr, KHh, nullptr, nullptr, SC,
                                      HD, HD, SS, HD / KC, 1.0f / 32.0f,
                                      (size_t)SS * HD, (size_t)SS * HD, (size_t)SS * SS);

    // 4) Softmax -> P hi fp16
    softmax_rows<<<dim3(SS, BB), 256>>>(mask, SC, Ph);

    // 5) Transpose V (hi) to [B][H][S]
    dim3 gt(HD / 32, SS / 32, BB);
    transpose_h<<<gt, dim3(32, 8)>>>(VHh, VTh);

    // 6) OUT = P @ VT^T (1-pass NT; k-chunks limited by causality)
    dim3 go(HD / 256, SS / 128, BB);
    gemmX<3, 1><<<go, 512, SMEMSZ>>>(Ph, nullptr, VTh, nullptr, nullptr, out,
                                     SS, SS, HD, 0, 1.f,
                                     (size_t)SS * SS, (size_t)HD * SS, (size_t)SS * HD);
}

// round 9
// speedup vs baseline: 1.9129x; 1.3955x over previous
#include <cuda_runtime.h>
#include <cuda_fp16.h>
#include <math.h>
#include <stdint.h>

// Problem dims (fixed)
#define BB 4
#define SS 2048
#define MD 1024
#define HD 1024
#define NT 8192   // BB*SS

// GEMM tiling: CTA 128x256, 16 warps (2x8) of 64x32, K-chunk 64, 1-pass fp16
#define KC 64
#define STG    49152          // A(16K) + B(32K)
#define NS     4              // pipeline stages
#define SMEMSZ (NS * STG)     // 192 KB

#define SWZ(o) ((o) ^ (((o) >> 3) & 0x70))

// ---------------------------------------------------------------------------
// Scratch (__device__ globals; allocation-free rule)
// ---------------------------------------------------------------------------
__device__ __align__(256) __half g_Xq_hi[(size_t)NT * MD];
__device__ __align__(256) __half g_Xk_hi[(size_t)NT * MD];
__device__ __align__(256) __half g_Xv_hi[(size_t)NT * MD];
__device__ __align__(256) __half g_Wq_hi[(size_t)HD * MD];
__device__ __align__(256) __half g_Wk_hi[(size_t)HD * MD];
__device__ __align__(256) __half g_Wv_hi[(size_t)HD * MD];
__device__ __align__(256) __half g_QH_hi[(size_t)NT * HD];
__device__ __align__(256) __half g_KH_hi[(size_t)NT * HD];
__device__ __align__(256) __half g_VH_hi[(size_t)NT * HD];
__device__ __align__(256) __half g_VT_hi[(size_t)BB * HD * SS];
__device__ __align__(256) float  g_SC[(size_t)BB * SS * SS];
__device__ __align__(256) __half g_P_hi[(size_t)BB * SS * SS];

// ---------------------------------------------------------------------------
__device__ __forceinline__ uint32_t smem_u32(const void* p) {
    uint32_t a;
    asm("{ .reg .u64 t; cvta.to.shared.u64 t, %1; cvt.u32.u64 %0, t; }"
        : "=r"(a) : "l"(p));
    return a;
}
#define CP16(dst, src) asm volatile("cp.async.cg.shared.global [%0], [%1], 16;" :: "r"(dst), "l"(src))
#define CP_COMMIT()    asm volatile("cp.async.commit_group;" ::: "memory")
#define CP_WAIT2()     asm volatile("cp.async.wait_group 2;" ::: "memory")

__device__ __forceinline__ void ldsm4(uint32_t r[4], uint32_t a) {
    asm volatile("ldmatrix.sync.aligned.m8n8.x4.shared.b16 {%0,%1,%2,%3}, [%4];"
                 : "=r"(r[0]), "=r"(r[1]), "=r"(r[2]), "=r"(r[3]) : "r"(a));
}
__device__ __forceinline__ void mma_f32(float d[4], const uint32_t a[4],
                                        uint32_t b0, uint32_t b1) {
    asm volatile(
        "mma.sync.aligned.m16n8k16.row.col.f32.f16.f16.f32 "
        "{%0,%1,%2,%3}, {%4,%5,%6,%7}, {%8,%9}, {%0,%1,%2,%3};"
        : "+f"(d[0]), "+f"(d[1]), "+f"(d[2]), "+f"(d[3])
        : "r"(a[0]), "r"(a[1]), "r"(a[2]), "r"(a[3]), "r"(b0), "r"(b1));
}

__device__ __forceinline__ uint32_t pack_h2(__half a, __half b) {
    union { __half2 v; uint32_t u; } t;
    t.v.x = a; t.v.y = b;
    return t.u;
}

// ---------------------------------------------------------------------------
// 1-pass fp16 mma.sync GEMM (NT): C = A*B^T [+ bias] [* alpha]
// A: [M,K] fp16 (lda). B: [N,K] fp16 (ldb).
// CTA 128x256, 16 warps (2x8) of 64x32, KC=64, 4-stage cp.async pipeline.
// MODE 1: out fp16 + bias (projections)
// MODE 2: out fp32 * alpha, causal tile skip 2*bn>bm (scores)
// MODE 3: out fp32, k-chunks limited to (bm+1)*2 (PV)
// ---------------------------------------------------------------------------
template <int MODE>
__global__ void __launch_bounds__(512, 1)
gemm1p(const __half* __restrict__ A, const __half* __restrict__ B,
       const float* __restrict__ bias,
       __half* __restrict__ Ch, float* __restrict__ Cf,
       int lda, int ldb, int ldc, int nkt0, float alpha,
       size_t sA, size_t sB, size_t sC)
{
    const int bm = blockIdx.y, bn = blockIdx.x, bz = blockIdx.z;
    if (MODE == 2 && 2 * bn > bm) return;
    const int nkt = (MODE == 3) ? (bm + 1) * 2 : nkt0;

    extern __shared__ char smem[];
    const uint32_t sb = smem_u32(smem);
    const int tid = threadIdx.x, lane = tid & 31, wid = tid >> 5;
    const int wm = wid >> 3, wn = wid & 7;

    const char* gA = (const char*)(A + (size_t)bz * sA + (size_t)(bm * 128) * lda);
    const char* gB = (const char*)(B + (size_t)bz * sB + (size_t)(bn * 256) * ldb);
    const size_t ldaB = (size_t)lda * 2, ldbB = (size_t)ldb * 2;

    auto load_chunk = [&](int c, int buf) {
        const uint32_t st = sb + buf * STG;
        const size_t cb = (size_t)c * 128;
#pragma unroll
        for (int i = 0; i < 2; ++i) {          // A: 128 rows x 128B
            const int idx = tid + i * 512;
            const int row = idx >> 3, seg = (idx & 7) * 16;
            CP16(st + SWZ(row * 128 + seg), gA + (size_t)row * ldaB + cb + seg);
        }
#pragma unroll
        for (int i = 0; i < 4; ++i) {          // B: 256 rows x 128B
            const int idx = tid + i * 512;
            const int row = idx >> 3, seg = (idx & 7) * 16;
            CP16(st + 16384 + SWZ(row * 128 + seg), gB + (size_t)row * ldbB + cb + seg);
        }
        CP_COMMIT();
    };

    float acc[4][4][4];
#pragma unroll
    for (int mi = 0; mi < 4; ++mi)
#pragma unroll
        for (int nf = 0; nf < 4; ++nf)
#pragma unroll
            for (int r = 0; r < 4; ++r) acc[mi][nf][r] = 0.f;

    const int lrow = lane & 15;
    const int lcb0 = (lane >> 4) * 16;
    const int arow = wm * 64 + lrow;
    const int brow = wn * 32 + lrow;

#pragma unroll
    for (int i = 0; i < NS - 1; ++i)
        if (i < nkt) load_chunk(i, i);
        else         CP_COMMIT();

    for (int c = 0; c < nkt; ++c) {
        CP_WAIT2();
        __syncthreads();
        if (c + NS - 1 < nkt) load_chunk(c + NS - 1, (c + NS - 1) % NS);
        else                  CP_COMMIT();   // keep wait-group count aligned

        const uint32_t st = sb + (c % NS) * STG;
#pragma unroll
        for (int kk = 0; kk < 4; ++kk) {
            const int cb = kk * 32 + lcb0;
            uint32_t a[4][4], bh[2][4];
#pragma unroll
            for (int mi = 0; mi < 4; ++mi)
                ldsm4(a[mi], st + SWZ((arow + mi * 16) * 128 + cb));
#pragma unroll
            for (int nj = 0; nj < 2; ++nj)
                ldsm4(bh[nj], st + 16384 + SWZ((brow + nj * 16) * 128 + cb));
#pragma unroll
            for (int mi = 0; mi < 4; ++mi)
#pragma unroll
                for (int nj = 0; nj < 2; ++nj) {
                    mma_f32(acc[mi][nj * 2 + 0], a[mi], bh[nj][0], bh[nj][2]);
                    mma_f32(acc[mi][nj * 2 + 1], a[mi], bh[nj][1], bh[nj][3]);
                }
        }
    }

    // ---- epilogue ----
    const int lr = lane >> 2;
    const int lc = (lane & 3) * 2;
#pragma unroll
    for (int mi = 0; mi < 4; ++mi) {
        const int row0 = bm * 128 + wm * 64 + mi * 16 + lr;
#pragma unroll
        for (int nf = 0; nf < 4; ++nf) {
            const int col = bn * 256 + wn * 32 + nf * 8 + lc;
            float* d = acc[mi][nf];
            if (MODE == 1) {
                const float b0 = bias[col], b1 = bias[col + 1];
                *(uint32_t*)(Ch + (size_t)row0 * ldc + col) =
                    pack_h2(__float2half_rn(d[0] + b0), __float2half_rn(d[1] + b1));
                *(uint32_t*)(Ch + (size_t)(row0 + 8) * ldc + col) =
                    pack_h2(__float2half_rn(d[2] + b0), __float2half_rn(d[3] + b1));
            } else {
                float* cp = Cf + (size_t)bz * sC;
                float2 o0 = { d[0] * alpha, d[1] * alpha };
                float2 o1 = { d[2] * alpha, d[3] * alpha };
                *(float2*)(cp + (size_t)row0 * ldc + col) = o0;
                *(float2*)(cp + (size_t)(row0 + 8) * ldc + col) = o1;
            }
        }
    }
}

// ---------------------------------------------------------------------------
// Fused convert: 6 tensors (q,k,v,Wq,Wk,Wv) -> fp16 hi, selected by blockIdx.y
// ---------------------------------------------------------------------------
__global__ void __launch_bounds__(256)
convert_hi6(const float* __restrict__ s0, const float* __restrict__ s1,
            const float* __restrict__ s2, const float* __restrict__ s3,
            const float* __restrict__ s4, const float* __restrict__ s5,
            __half* __restrict__ h0, __half* __restrict__ h1,
            __half* __restrict__ h2, __half* __restrict__ h3,
            __half* __restrict__ h4, __half* __restrict__ h5,
            size_t nX4, size_t nW4)
{
    const int t = blockIdx.y;
    const size_t n4 = (t < 3) ? nX4 : nW4;
    size_t i = (size_t)blockIdx.x * blockDim.x + threadIdx.x;
    if (i >= n4) return;
    const float* src = (t == 0) ? s0 : (t == 1) ? s1 : (t == 2) ? s2
                     : (t == 3) ? s3 : (t == 4) ? s4 : s5;
    __half* hi = (t == 0) ? h0 : (t == 1) ? h1 : (t == 2) ? h2
               : (t == 3) ? h3 : (t == 4) ? h4 : h5;
    float4 x = ((const float4*)src)[i];
    union { __half h[4]; uint2 u; } H;
    H.h[0] = __float2half_rn(x.x);
    H.h[1] = __float2half_rn(x.y);
    H.h[2] = __float2half_rn(x.z);
    H.h[3] = __float2half_rn(x.w);
    ((uint2*)hi)[i] = H.u;
}

// ---------------------------------------------------------------------------
// fp16 transpose per batch: src [B*S, H] -> dst [B][H][S]
// ---------------------------------------------------------------------------
__global__ void __launch_bounds__(256)
transpose_h(const __half* __restrict__ src, __half* __restrict__ dst)
{
    __shared__ __half t[32][33];
    const int b = blockIdx.z;
    const int h0 = blockIdx.x * 32, s0 = blockIdx.y * 32;
    const int tx = threadIdx.x, ty = threadIdx.y;  // 32 x 8
#pragma unroll
    for (int i = 0; i < 4; ++i)
        t[ty + i * 8][tx] = src[((size_t)b * SS + s0 + ty + i * 8) * HD + h0 + tx];
    __syncthreads();
#pragma unroll
    for (int i = 0; i < 4; ++i)
        dst[((size_t)b * HD + h0 + ty + i * 8) * SS + s0 + tx] = t[tx][ty + i * 8];
}

// ---------------------------------------------------------------------------
// Masked causal softmax: SC fp32 -> P fp16, zero-filled to 128-boundary.
// ---------------------------------------------------------------------------
__global__ void __launch_bounds__(256)
softmax_rows(const int* __restrict__ mask, const float* __restrict__ SC,
             __half* __restrict__ Phi)
{
    const int b = blockIdx.y;
    const int i = blockIdx.x;
    const size_t rowoff = ((size_t)b * SS + i) * SS;
    const float* row = SC + rowoff;
    const int* mrow = mask + (size_t)b * SS;
    const int tid = threadIdx.x;
    const int nvalid = i + 1;
    const int nfill = ((i >> 7) + 1) << 7;

    float vals[8];
    float vmax = -INFINITY;
#pragma unroll
    for (int t = 0; t < 8; ++t) {
        int j = tid + t * 256;
        float s = -INFINITY;
        if (j < nvalid) {
            s = row[j];
            if (mrow[j] == 0) s = -1e9f;
        }
        vals[t] = s;
        vmax = fmaxf(vmax, s);
    }

    __shared__ float red[8];
#pragma unroll
    for (int o = 16; o; o >>= 1) vmax = fmaxf(vmax, __shfl_xor_sync(~0u, vmax, o));
    if ((tid & 31) == 0) red[tid >> 5] = vmax;
    __syncthreads();
    if (tid < 32) {
        float x = (tid < 8) ? red[tid] : -INFINITY;
#pragma unroll
        for (int o = 4; o; o >>= 1) x = fmaxf(x, __shfl_xor_sync(~0u, x, o));
        if (tid == 0) red[0] = x;
    }
    __syncthreads();
    vmax = red[0];
    __syncthreads();

    float lsum = 0.f;
#pragma unroll
    for (int t = 0; t < 8; ++t) {
        float e = __expf(vals[t] - vmax);
        vals[t] = e;
        lsum += e;
    }
#pragma unroll
    for (int o = 16; o; o >>= 1) lsum += __shfl_xor_sync(~0u, lsum, o);
    if ((tid & 31) == 0) red[tid >> 5] = lsum;
    __syncthreads();
    if (tid < 32) {
        float x = (tid < 8) ? red[tid] : 0.f;
#pragma unroll
        for (int o = 4; o; o >>= 1) x += __shfl_xor_sync(~0u, x, o);
        if (tid == 0) red[0] = x;
    }
    __syncthreads();
    const float rinv = 1.0f / red[0];

#pragma unroll
    for (int t = 0; t < 8; ++t) {
        int j = tid + t * 256;
        if (j < nfill)
            Phi[rowoff + j] = __float2half_rn(vals[t] * rinv);  // 0 for j > i
    }
}

// ---------------------------------------------------------------------------
extern "C" void kernel_launch(void* const* d_in, const int* in_sizes, int n_in,
                              void* d_out, int out_size)
{
    (void)in_sizes; (void)n_in; (void)out_size;

    const float* q    = (const float*)d_in[0];
    const float* k    = (const float*)d_in[1];
    const float* v    = (const float*)d_in[2];
    const int*   mask = (const int*)  d_in[3];
    const float* Wq   = (const float*)d_in[4];
    const float* bq   = (const float*)d_in[5];
    const float* Wk   = (const float*)d_in[6];
    const float* bk   = (const float*)d_in[7];
    const float* Wv   = (const float*)d_in[8];
    const float* bv   = (const float*)d_in[9];
    float* out = (float*)d_out;

    static bool init = false;
    static __half *Xqh, *Xkh, *Xvh, *Wqh, *Wkh, *Wvh;
    static __half *QHh, *KHh, *VHh, *VTh, *Ph;
    static float *SC;
    if (!init) {
        void* p;
        cudaGetSymbolAddress(&p, g_Xq_hi); Xqh = (__half*)p;
        cudaGetSymbolAddress(&p, g_Xk_hi); Xkh = (__half*)p;
        cudaGetSymbolAddress(&p, g_Xv_hi); Xvh = (__half*)p;
        cudaGetSymbolAddress(&p, g_Wq_hi); Wqh = (__half*)p;
        cudaGetSymbolAddress(&p, g_Wk_hi); Wkh = (__half*)p;
        cudaGetSymbolAddress(&p, g_Wv_hi); Wvh = (__half*)p;
        cudaGetSymbolAddress(&p, g_QH_hi); QHh = (__half*)p;
        cudaGetSymbolAddress(&p, g_KH_hi); KHh = (__half*)p;
        cudaGetSymbolAddress(&p, g_VH_hi); VHh = (__half*)p;
        cudaGetSymbolAddress(&p, g_VT_hi); VTh = (__half*)p;
        cudaGetSymbolAddress(&p, g_P_hi);  Ph  = (__half*)p;
        cudaGetSymbolAddress(&p, g_SC);    SC  = (float*)p;
        cudaFuncSetAttribute((const void*)gemm1p<1>, cudaFuncAttributeMaxDynamicSharedMemorySize, SMEMSZ);
        cudaFuncSetAttribute((const void*)gemm1p<2>, cudaFuncAttributeMaxDynamicSharedMemorySize, SMEMSZ);
        cudaFuncSetAttribute((const void*)gemm1p<3>, cudaFuncAttributeMaxDynamicSharedMemorySize, SMEMSZ);
        init = true;
    }

    // 1) Convert all 6 inputs to fp16 in one launch
    const size_t nX4 = (size_t)NT * MD / 4;
    const size_t nW4 = (size_t)HD * MD / 4;
    convert_hi6<<<dim3((unsigned)((nX4 + 255) / 256), 6), 256>>>(
        q, k, v, Wq, Wk, Wv, Xqh, Xkh, Xvh, Wqh, Wkh, Wvh, nX4, nW4);

    // 2) Projections (1-pass fp16)
    dim3 gproj(HD / 256, NT / 128, 1);
    gemm1p<1><<<gproj, 512, SMEMSZ>>>(Xqh, Wqh, bq, QHh, nullptr,
                                      MD, MD, HD, MD / KC, 1.f, 0, 0, 0);
    gemm1p<1><<<gproj, 512, SMEMSZ>>>(Xkh, Wkh, bk, KHh, nullptr,
                                      MD, MD, HD, MD / KC, 1.f, 0, 0, 0);
    gemm1p<1><<<gproj, 512, SMEMSZ>>>(Xvh, Wvh, bv, VHh, nullptr,
                                      MD, MD, HD, MD / KC, 1.f, 0, 0, 0);

    // 3) Transpose V to [B][H][S]
    dim3 gt(HD / 32, SS / 32, BB);
    transpose_h<<<gt, dim3(32, 8)>>>(VHh, VTh);

    // 4) Scores (1-pass, causal skip) — 6th launch: ncu -s 5 captures this
    dim3 gsc(SS / 256, SS / 128, BB);
    gemm1p<2><<<gsc, 512, SMEMSZ>>>(QHh, KHh, nullptr, nullptr, SC,
                                    HD, HD, SS, HD / KC, 1.0f / 32.0f,
                                    (size_t)SS * HD, (size_t)SS * HD, (size_t)SS * SS);

    // 5) Softmax -> P fp16
    softmax_rows<<<dim3(SS, BB), 256>>>(mask, SC, Ph);

    // 6) OUT = P @ VT^T (1-pass NT; k-chunks limited by causality)
    dim3 go(HD / 256, SS / 128, BB);
    gemm1p<3><<<go, 512, SMEMSZ>>>(Ph, VTh, nullptr, nullptr, out,
                                   SS, SS, HD, 0, 1.f,
                                   (size_t)SS * SS, (size_t)HD * SS, (size_t)SS * HD);
}

// round 10
// speedup vs baseline: 1.9736x; 1.0317x over previous
#include <cuda_runtime.h>
#include <cuda_fp16.h>
#include <math.h>
#include <stdint.h>

// Problem dims (fixed)
#define BB 4
#define SS 2048
#define MD 1024
#define HD 1024
#define NT 8192   // BB*SS

// GEMM tiling: CTA 128x256, 8 warps (2x4) of 64x64, K-chunk 64, 1-pass fp16
#define KC 64
#define STG    49152          // A(16K) + B(32K)
#define NS     4              // pipeline stages
#define SMEMSZ (NS * STG)     // 192 KB

#define SWZ(o) ((o) ^ (((o) >> 3) & 0x70))

// ---------------------------------------------------------------------------
// Scratch (__device__ globals; allocation-free rule)
// ---------------------------------------------------------------------------
__device__ __align__(256) __half g_Xq_hi[(size_t)NT * MD];
__device__ __align__(256) __half g_Xk_hi[(size_t)NT * MD];
__device__ __align__(256) __half g_Xv_hi[(size_t)NT * MD];
__device__ __align__(256) __half g_Wq_hi[(size_t)HD * MD];
__device__ __align__(256) __half g_Wk_hi[(size_t)HD * MD];
__device__ __align__(256) __half g_Wv_hi[(size_t)HD * MD];
__device__ __align__(256) __half g_QH_hi[(size_t)NT * HD];
__device__ __align__(256) __half g_KH_hi[(size_t)NT * HD];
__device__ __align__(256) __half g_VH_hi[(size_t)NT * HD];
__device__ __align__(256) __half g_VT_hi[(size_t)BB * HD * SS];
__device__ __align__(256) float  g_SC[(size_t)BB * SS * SS];
__device__ __align__(256) __half g_P_hi[(size_t)BB * SS * SS];

// ---------------------------------------------------------------------------
__device__ __forceinline__ uint32_t smem_u32(const void* p) {
    uint32_t a;
    asm("{ .reg .u64 t; cvta.to.shared.u64 t, %1; cvt.u32.u64 %0, t; }"
        : "=r"(a) : "l"(p));
    return a;
}
#define CP16(dst, src) asm volatile("cp.async.cg.shared.global [%0], [%1], 16;" :: "r"(dst), "l"(src))
#define CP_COMMIT()    asm volatile("cp.async.commit_group;" ::: "memory")
#define CP_WAIT2()     asm volatile("cp.async.wait_group 2;" ::: "memory")

__device__ __forceinline__ void ldsm4(uint32_t r[4], uint32_t a) {
    asm volatile("ldmatrix.sync.aligned.m8n8.x4.shared.b16 {%0,%1,%2,%3}, [%4];"
                 : "=r"(r[0]), "=r"(r[1]), "=r"(r[2]), "=r"(r[3]) : "r"(a));
}
__device__ __forceinline__ void mma_f32(float d[4], const uint32_t a[4],
                                        uint32_t b0, uint32_t b1) {
    asm volatile(
        "mma.sync.aligned.m16n8k16.row.col.f32.f16.f16.f32 "
        "{%0,%1,%2,%3}, {%4,%5,%6,%7}, {%8,%9}, {%0,%1,%2,%3};"
        : "+f"(d[0]), "+f"(d[1]), "+f"(d[2]), "+f"(d[3])
        : "r"(a[0]), "r"(a[1]), "r"(a[2]), "r"(a[3]), "r"(b0), "r"(b1));
}

__device__ __forceinline__ uint32_t pack_h2(__half a, __half b) {
    union { __half2 v; uint32_t u; } t;
    t.v.x = a; t.v.y = b;
    return t.u;
}

// ---------------------------------------------------------------------------
// 1-pass fp16 mma.sync GEMM (NT): C = A*B^T [+ bias] [* alpha]
// A: [M,K] fp16 (lda). B: [N,K] fp16 (ldb).
// CTA 128x256, 8 warps (2x4) of 64x64, KC=64, 4-stage cp.async pipeline.
// MODE 1: out fp16 + bias (projections)
// MODE 2: out fp32 * alpha, causal tile skip 2*bn>bm (scores)
// MODE 3: out fp32, k-chunks limited to (bm+1)*2 (PV)
// ---------------------------------------------------------------------------
template <int MODE>
__global__ void __launch_bounds__(256, 1)
gemm1p(const __half* __restrict__ A, const __half* __restrict__ B,
       const float* __restrict__ bias,
       __half* __restrict__ Ch, float* __restrict__ Cf,
       int lda, int ldb, int ldc, int nkt0, float alpha,
       size_t sA, size_t sB, size_t sC)
{
    const int bm = blockIdx.y, bn = blockIdx.x, bz = blockIdx.z;
    if (MODE == 2 && 2 * bn > bm) return;
    const int nkt = (MODE == 3) ? (bm + 1) * 2 : nkt0;

    extern __shared__ char smem[];
    const uint32_t sb = smem_u32(smem);
    const int tid = threadIdx.x, lane = tid & 31, wid = tid >> 5;
    const int wm = wid >> 2, wn = wid & 3;

    const char* gA = (const char*)(A + (size_t)bz * sA + (size_t)(bm * 128) * lda);
    const char* gB = (const char*)(B + (size_t)bz * sB + (size_t)(bn * 256) * ldb);
    const size_t ldaB = (size_t)lda * 2, ldbB = (size_t)ldb * 2;

    auto load_chunk = [&](int c, int buf) {
        const uint32_t st = sb + buf * STG;
        const size_t cb = (size_t)c * 128;
#pragma unroll
        for (int i = 0; i < 4; ++i) {          // A: 128 rows x 128B
            const int idx = tid + i * 256;
            const int row = idx >> 3, seg = (idx & 7) * 16;
            CP16(st + SWZ(row * 128 + seg), gA + (size_t)row * ldaB + cb + seg);
        }
#pragma unroll
        for (int i = 0; i < 8; ++i) {          // B: 256 rows x 128B
            const int idx = tid + i * 256;
            const int row = idx >> 3, seg = (idx & 7) * 16;
            CP16(st + 16384 + SWZ(row * 128 + seg), gB + (size_t)row * ldbB + cb + seg);
        }
        CP_COMMIT();
    };

    float acc[4][8][4];
#pragma unroll
    for (int mi = 0; mi < 4; ++mi)
#pragma unroll
        for (int nf = 0; nf < 8; ++nf)
#pragma unroll
            for (int r = 0; r < 4; ++r) acc[mi][nf][r] = 0.f;

    const int lrow = lane & 15;
    const int lcb0 = (lane >> 4) * 16;
    const int arow = wm * 64 + lrow;
    const int brow = wn * 64 + lrow;

#pragma unroll
    for (int i = 0; i < NS - 1; ++i)
        if (i < nkt) load_chunk(i, i);
        else         CP_COMMIT();

    for (int c = 0; c < nkt; ++c) {
        CP_WAIT2();
        __syncthreads();
        if (c + NS - 1 < nkt) load_chunk(c + NS - 1, (c + NS - 1) % NS);
        else                  CP_COMMIT();   // keep wait-group count aligned

        const uint32_t st = sb + (c % NS) * STG;
#pragma unroll
        for (int kk = 0; kk < 4; ++kk) {
            const int cb = kk * 32 + lcb0;
            uint32_t a[4][4], bh[4][4];
#pragma unroll
            for (int mi = 0; mi < 4; ++mi)
                ldsm4(a[mi], st + SWZ((arow + mi * 16) * 128 + cb));
#pragma unroll
            for (int nj = 0; nj < 4; ++nj)
                ldsm4(bh[nj], st + 16384 + SWZ((brow + nj * 16) * 128 + cb));
#pragma unroll
            for (int mi = 0; mi < 4; ++mi)
#pragma unroll
                for (int nj = 0; nj < 4; ++nj) {
                    mma_f32(acc[mi][nj * 2 + 0], a[mi], bh[nj][0], bh[nj][2]);
                    mma_f32(acc[mi][nj * 2 + 1], a[mi], bh[nj][1], bh[nj][3]);
                }
        }
    }

    // ---- epilogue ----
    const int lr = lane >> 2;
    const int lc = (lane & 3) * 2;
#pragma unroll
    for (int mi = 0; mi < 4; ++mi) {
        const int row0 = bm * 128 + wm * 64 + mi * 16 + lr;
#pragma unroll
        for (int nf = 0; nf < 8; ++nf) {
            const int col = bn * 256 + wn * 64 + nf * 8 + lc;
            float* d = acc[mi][nf];
            if (MODE == 1) {
                const float b0 = bias[col], b1 = bias[col + 1];
                *(uint32_t*)(Ch + (size_t)row0 * ldc + col) =
                    pack_h2(__float2half_rn(d[0] + b0), __float2half_rn(d[1] + b1));
                *(uint32_t*)(Ch + (size_t)(row0 + 8) * ldc + col) =
                    pack_h2(__float2half_rn(d[2] + b0), __float2half_rn(d[3] + b1));
            } else {
                float* cp = Cf + (size_t)bz * sC;
                float2 o0 = { d[0] * alpha, d[1] * alpha };
                float2 o1 = { d[2] * alpha, d[3] * alpha };
                *(float2*)(cp + (size_t)row0 * ldc + col) = o0;
                *(float2*)(cp + (size_t)(row0 + 8) * ldc + col) = o1;
            }
        }
    }
}

// ---------------------------------------------------------------------------
// Fused convert: 6 tensors (q,k,v,Wq,Wk,Wv) -> fp16, selected by blockIdx.y
// ---------------------------------------------------------------------------
__global__ void __launch_bounds__(256)
convert_hi6(const float* __restrict__ s0, const float* __restrict__ s1,
            const float* __restrict__ s2, const float* __restrict__ s3,
            const float* __restrict__ s4, const float* __restrict__ s5,
            __half* __restrict__ h0, __half* __restrict__ h1,
            __half* __restrict__ h2, __half* __restrict__ h3,
            __half* __restrict__ h4, __half* __restrict__ h5,
            size_t nX4, size_t nW4)
{
    const int t = blockIdx.y;
    const size_t n4 = (t < 3) ? nX4 : nW4;
    size_t i = (size_t)blockIdx.x * blockDim.x + threadIdx.x;
    if (i >= n4) return;
    const float* src = (t == 0) ? s0 : (t == 1) ? s1 : (t == 2) ? s2
                     : (t == 3) ? s3 : (t == 4) ? s4 : s5;
    __half* hi = (t == 0) ? h0 : (t == 1) ? h1 : (t == 2) ? h2
               : (t == 3) ? h3 : (t == 4) ? h4 : h5;
    float4 x = ((const float4*)src)[i];
    union { __half h[4]; uint2 u; } H;
    H.h[0] = __float2half_rn(x.x);
    H.h[1] = __float2half_rn(x.y);
    H.h[2] = __float2half_rn(x.z);
    H.h[3] = __float2half_rn(x.w);
    ((uint2*)hi)[i] = H.u;
}

// ---------------------------------------------------------------------------
// fp16 transpose per batch: src [B*S, H] -> dst [B][H][S]
// ---------------------------------------------------------------------------
__global__ void __launch_bounds__(256)
transpose_h(const __half* __restrict__ src, __half* __restrict__ dst)
{
    __shared__ __half t[32][33];
    const int b = blockIdx.z;
    const int h0 = blockIdx.x * 32, s0 = blockIdx.y * 32;
    const int tx = threadIdx.x, ty = threadIdx.y;  // 32 x 8
#pragma unroll
    for (int i = 0; i < 4; ++i)
        t[ty + i * 8][tx] = src[((size_t)b * SS + s0 + ty + i * 8) * HD + h0 + tx];
    __syncthreads();
#pragma unroll
    for (int i = 0; i < 4; ++i)
        dst[((size_t)b * HD + h0 + ty + i * 8) * SS + s0 + tx] = t[tx][ty + i * 8];
}

// ---------------------------------------------------------------------------
// Masked causal softmax: SC fp32 -> P fp16, zero-filled to 128-boundary.
// ---------------------------------------------------------------------------
__global__ void __launch_bounds__(256)
softmax_rows(const int* __restrict__ mask, const float* __restrict__ SC,
             __half* __restrict__ Phi)
{
    const int b = blockIdx.y;
    const int i = blockIdx.x;
    const size_t rowoff = ((size_t)b * SS + i) * SS;
    const float* row = SC + rowoff;
    const int* mrow = mask + (size_t)b * SS;
    const int tid = threadIdx.x;
    const int nvalid = i + 1;
    const int nfill = ((i >> 7) + 1) << 7;

    float vals[8];
    float vmax = -INFINITY;
#pragma unroll
    for (int t = 0; t < 8; ++t) {
        int j = tid + t * 256;
        float s = -INFINITY;
        if (j < nvalid) {
            s = row[j];
            if (mrow[j] == 0) s = -1e9f;
        }
        vals[t] = s;
        vmax = fmaxf(vmax, s);
    }

    __shared__ float red[8];
#pragma unroll
    for (int o = 16; o; o >>= 1) vmax = fmaxf(vmax, __shfl_xor_sync(~0u, vmax, o));
    if ((tid & 31) == 0) red[tid >> 5] = vmax;
    __syncthreads();
    if (tid < 32) {
        float x = (tid < 8) ? red[tid] : -INFINITY;
#pragma unroll
        for (int o = 4; o; o >>= 1) x = fmaxf(x, __shfl_xor_sync(~0u, x, o));
        if (tid == 0) red[0] = x;
    }
    __syncthreads();
    vmax = red[0];
    __syncthreads();

    float lsum = 0.f;
#pragma unroll
    for (int t = 0; t < 8; ++t) {
        float e = __expf(vals[t] - vmax);
        vals[t] = e;
        lsum += e;
    }
#pragma unroll
    for (int o = 16; o; o >>= 1) lsum += __shfl_xor_sync(~0u, lsum, o);
    if ((tid & 31) == 0) red[tid >> 5] = lsum;
    __syncthreads();
    if (tid < 32) {
        float x = (tid < 8) ? red[tid] : 0.f;
#pragma unroll
        for (int o = 4; o; o >>= 1) x += __shfl_xor_sync(~0u, x, o);
        if (tid == 0) red[0] = x;
    }
    __syncthreads();
    const float rinv = 1.0f / red[0];

#pragma unroll
    for (int t = 0; t < 8; ++t) {
        int j = tid + t * 256;
        if (j < nfill)
            Phi[rowoff + j] = __float2half_rn(vals[t] * rinv);  // 0 for j > i
    }
}

// ---------------------------------------------------------------------------
extern "C" void kernel_launch(void* const* d_in, const int* in_sizes, int n_in,
                              void* d_out, int out_size)
{
    (void)in_sizes; (void)n_in; (void)out_size;

    const float* q    = (const float*)d_in[0];
    const float* k    = (const float*)d_in[1];
    const float* v    = (const float*)d_in[2];
    const int*   mask = (const int*)  d_in[3];
    const float* Wq   = (const float*)d_in[4];
    const float* bq   = (const float*)d_in[5];
    const float* Wk   = (const float*)d_in[6];
    const float* bk   = (const float*)d_in[7];
    const float* Wv   = (const float*)d_in[8];
    const float* bv   = (const float*)d_in[9];
    float* out = (float*)d_out;

    static bool init = false;
    static __half *Xqh, *Xkh, *Xvh, *Wqh, *Wkh, *Wvh;
    static __half *QHh, *KHh, *VHh, *VTh, *Ph;
    static float *SC;
    if (!init) {
        void* p;
        cudaGetSymbolAddress(&p, g_Xq_hi); Xqh = (__half*)p;
        cudaGetSymbolAddress(&p, g_Xk_hi); Xkh = (__half*)p;
        cudaGetSymbolAddress(&p, g_Xv_hi); Xvh = (__half*)p;
        cudaGetSymbolAddress(&p, g_Wq_hi); Wqh = (__half*)p;
        cudaGetSymbolAddress(&p, g_Wk_hi); Wkh = (__half*)p;
        cudaGetSymbolAddress(&p, g_Wv_hi); Wvh = (__half*)p;
        cudaGetSymbolAddress(&p, g_QH_hi); QHh = (__half*)p;
        cudaGetSymbolAddress(&p, g_KH_hi); KHh = (__half*)p;
        cudaGetSymbolAddress(&p, g_VH_hi); VHh = (__half*)p;
        cudaGetSymbolAddress(&p, g_VT_hi); VTh = (__half*)p;
        cudaGetSymbolAddress(&p, g_P_hi);  Ph  = (__half*)p;
        cudaGetSymbolAddress(&p, g_SC);    SC  = (float*)p;
        cudaFuncSetAttribute((const void*)gemm1p<1>, cudaFuncAttributeMaxDynamicSharedMemorySize, SMEMSZ);
        cudaFuncSetAttribute((const void*)gemm1p<2>, cudaFuncAttributeMaxDynamicSharedMemorySize, SMEMSZ);
        cudaFuncSetAttribute((const void*)gemm1p<3>, cudaFuncAttributeMaxDynamicSharedMemorySize, SMEMSZ);
        init = true;
    }

    // 1) Convert all 6 inputs to fp16 in one launch
    const size_t nX4 = (size_t)NT * MD / 4;
    const size_t nW4 = (size_t)HD * MD / 4;
    convert_hi6<<<dim3((unsigned)((nX4 + 255) / 256), 6), 256>>>(
        q, k, v, Wq, Wk, Wv, Xqh, Xkh, Xvh, Wqh, Wkh, Wvh, nX4, nW4);

    // 2) Projections (1-pass fp16)
    dim3 gproj(HD / 256, NT / 128, 1);
    gemm1p<1><<<gproj, 256, SMEMSZ>>>(Xqh, Wqh, bq, QHh, nullptr,
                                      MD, MD, HD, MD / KC, 1.f, 0, 0, 0);
    gemm1p<1><<<gproj, 256, SMEMSZ>>>(Xkh, Wkh, bk, KHh, nullptr,
                                      MD, MD, HD, MD / KC, 1.f, 0, 0, 0);
    gemm1p<1><<<gproj, 256, SMEMSZ>>>(Xvh, Wvh, bv, VHh, nullptr,
                                      MD, MD, HD, MD / KC, 1.f, 0, 0, 0);

    // 3) Transpose V to [B][H][S]
    dim3 gt(HD / 32, SS / 32, BB);
    transpose_h<<<gt, dim3(32, 8)>>>(VHh, VTh);

    // 4) Scores (1-pass, causal skip) — 6th launch: ncu -s 5 captures this
    dim3 gsc(SS / 256, SS / 128, BB);
    gemm1p<2><<<gsc, 256, SMEMSZ>>>(QHh, KHh, nullptr, nullptr, SC,
                                    HD, HD, SS, HD / KC, 1.0f / 32.0f,
                                    (size_t)SS * HD, (size_t)SS * HD, (size_t)SS * SS);

    // 5) Softmax -> P fp16
    softmax_rows<<<dim3(SS, BB), 256>>>(mask, SC, Ph);

    // 6) OUT = P @ VT^T (1-pass NT; k-chunks limited by causality)
    dim3 go(HD / 256, SS / 128, BB);
    gemm1p<3><<<go, 256, SMEMSZ>>>(Ph, VTh, nullptr, nullptr, out,
                                   SS, SS, HD, 0, 1.f,
                                   (size_t)SS * SS, (size_t)HD * SS, (size_t)SS * HD);
}

// round 11
// speedup vs baseline: 2.0383x; 1.0328x over previous
#include <cuda_runtime.h>
#include <cuda_fp16.h>
#include <math.h>
#include <stdint.h>

// Problem dims (fixed)
#define BB 4
#define SS 2048
#define MD 1024
#define HD 1024
#define NT 8192   // BB*SS

// GEMM tiling: CTA 128x256, 8 warps (2x4) of 64x64, K-chunk 64, 1-pass fp16
#define KC 64
#define STG    49152          // A(16K) + B(32K)
#define NS     4              // pipeline stages
#define SMEMSZ (NS * STG)     // 192 KB

#define SWZ(o) ((o) ^ (((o) >> 3) & 0x70))

// ---------------------------------------------------------------------------
// Scratch (__device__ globals; allocation-free rule)
// ---------------------------------------------------------------------------
__device__ __align__(256) __half g_Xq_hi[(size_t)NT * MD];
__device__ __align__(256) __half g_Xk_hi[(size_t)NT * MD];
__device__ __align__(256) __half g_Xv_hi[(size_t)NT * MD];
__device__ __align__(256) __half g_Wq_hi[(size_t)HD * MD];
__device__ __align__(256) __half g_Wk_hi[(size_t)HD * MD];
__device__ __align__(256) __half g_Wv_hi[(size_t)HD * MD];
__device__ __align__(256) __half g_QH_hi[(size_t)NT * HD];
__device__ __align__(256) __half g_KH_hi[(size_t)NT * HD];
__device__ __align__(256) __half g_VH_hi[(size_t)NT * HD];
__device__ __align__(256) __half g_VT_hi[(size_t)BB * HD * SS];
__device__ __align__(256) float  g_SC[(size_t)BB * SS * SS];
__device__ __align__(256) __half g_P_hi[(size_t)BB * SS * SS];

// ---------------------------------------------------------------------------
__device__ __forceinline__ uint32_t smem_u32(const void* p) {
    uint32_t a;
    asm("{ .reg .u64 t; cvta.to.shared.u64 t, %1; cvt.u32.u64 %0, t; }"
        : "=r"(a) : "l"(p));
    return a;
}
#define CP16(dst, src) asm volatile("cp.async.cg.shared.global [%0], [%1], 16;" :: "r"(dst), "l"(src))
#define CP_COMMIT()    asm volatile("cp.async.commit_group;" ::: "memory")
#define CP_WAIT2()     asm volatile("cp.async.wait_group 2;" ::: "memory")

__device__ __forceinline__ void ldsm4(uint32_t r[4], uint32_t a) {
    asm volatile("ldmatrix.sync.aligned.m8n8.x4.shared.b16 {%0,%1,%2,%3}, [%4];"
                 : "=r"(r[0]), "=r"(r[1]), "=r"(r[2]), "=r"(r[3]) : "r"(a));
}
__device__ __forceinline__ void mma_f32(float d[4], const uint32_t a[4],
                                        uint32_t b0, uint32_t b1) {
    asm volatile(
        "mma.sync.aligned.m16n8k16.row.col.f32.f16.f16.f32 "
        "{%0,%1,%2,%3}, {%4,%5,%6,%7}, {%8,%9}, {%0,%1,%2,%3};"
        : "+f"(d[0]), "+f"(d[1]), "+f"(d[2]), "+f"(d[3])
        : "r"(a[0]), "r"(a[1]), "r"(a[2]), "r"(a[3]), "r"(b0), "r"(b1));
}

__device__ __forceinline__ uint32_t pack_h2(__half a, __half b) {
    union { __half2 v; uint32_t u; } t;
    t.v.x = a; t.v.y = b;
    return t.u;
}

// ---------------------------------------------------------------------------
// Shared GEMM mainloop body (1-pass fp16 NT): acc += A*B^T over nkt chunks.
// ---------------------------------------------------------------------------
struct GemmCtx {
    const char* gA;
    const char* gB;
    size_t ldaB, ldbB;
};

__device__ __forceinline__ void gemm_mainloop(
    const GemmCtx& cx, uint32_t sb, int tid, int lane, int wm, int wn,
    int nkt, float acc[4][8][4])
{
    auto load_chunk = [&](int c, int buf) {
        const uint32_t st = sb + buf * STG;
        const size_t cb = (size_t)c * 128;
#pragma unroll
        for (int i = 0; i < 4; ++i) {          // A: 128 rows x 128B
            const int idx = tid + i * 256;
            const int row = idx >> 3, seg = (idx & 7) * 16;
            CP16(st + SWZ(row * 128 + seg), cx.gA + (size_t)row * cx.ldaB + cb + seg);
        }
#pragma unroll
        for (int i = 0; i < 8; ++i) {          // B: 256 rows x 128B
            const int idx = tid + i * 256;
            const int row = idx >> 3, seg = (idx & 7) * 16;
            CP16(st + 16384 + SWZ(row * 128 + seg), cx.gB + (size_t)row * cx.ldbB + cb + seg);
        }
        CP_COMMIT();
    };

    const int lrow = lane & 15;
    const int lcb0 = (lane >> 4) * 16;
    const int arow = wm * 64 + lrow;
    const int brow = wn * 64 + lrow;

#pragma unroll
    for (int i = 0; i < NS - 1; ++i)
        if (i < nkt) load_chunk(i, i);
        else         CP_COMMIT();

    for (int c = 0; c < nkt; ++c) {
        CP_WAIT2();
        __syncthreads();
        if (c + NS - 1 < nkt) load_chunk(c + NS - 1, (c + NS - 1) % NS);
        else                  CP_COMMIT();   // keep wait-group count aligned

        const uint32_t st = sb + (c % NS) * STG;
#pragma unroll
        for (int kk = 0; kk < 4; ++kk) {
            const int cb = kk * 32 + lcb0;
            uint32_t a[4][4], bh[4][4];
#pragma unroll
            for (int mi = 0; mi < 4; ++mi)
                ldsm4(a[mi], st + SWZ((arow + mi * 16) * 128 + cb));
#pragma unroll
            for (int nj = 0; nj < 4; ++nj)
                ldsm4(bh[nj], st + 16384 + SWZ((brow + nj * 16) * 128 + cb));
#pragma unroll
            for (int mi = 0; mi < 4; ++mi)
#pragma unroll
                for (int nj = 0; nj < 4; ++nj) {
                    mma_f32(acc[mi][nj * 2 + 0], a[mi], bh[nj][0], bh[nj][2]);
                    mma_f32(acc[mi][nj * 2 + 1], a[mi], bh[nj][1], bh[nj][3]);
                }
        }
    }
}

// ---------------------------------------------------------------------------
// Fused projection GEMM: grid.z in {0,1,2} selects (X, W, bias, out) for q/k/v.
// One launch, 768 CTAs -> minimal wave quantization.
// ---------------------------------------------------------------------------
__global__ void __launch_bounds__(256, 1)
gemm_proj3(const __half* __restrict__ A0, const __half* __restrict__ A1,
           const __half* __restrict__ A2,
           const __half* __restrict__ B0, const __half* __restrict__ B1,
           const __half* __restrict__ B2,
           const float* __restrict__ b0p, const float* __restrict__ b1p,
           const float* __restrict__ b2p,
           __half* __restrict__ C0, __half* __restrict__ C1,
           __half* __restrict__ C2)
{
    const int bm = blockIdx.y, bn = blockIdx.x, t = blockIdx.z;
    const __half* A   = (t == 0) ? A0 : (t == 1) ? A1 : A2;
    const __half* B   = (t == 0) ? B0 : (t == 1) ? B1 : B2;
    const float* bias = (t == 0) ? b0p : (t == 1) ? b1p : b2p;
    __half* Ch        = (t == 0) ? C0 : (t == 1) ? C1 : C2;

    extern __shared__ char smem[];
    const uint32_t sb = smem_u32(smem);
    const int tid = threadIdx.x, lane = tid & 31, wid = tid >> 5;
    const int wm = wid >> 2, wn = wid & 3;

    GemmCtx cx;
    cx.gA = (const char*)(A + (size_t)(bm * 128) * MD);
    cx.gB = (const char*)(B + (size_t)(bn * 256) * MD);
    cx.ldaB = (size_t)MD * 2;
    cx.ldbB = (size_t)MD * 2;

    float acc[4][8][4];
#pragma unroll
    for (int mi = 0; mi < 4; ++mi)
#pragma unroll
        for (int nf = 0; nf < 8; ++nf)
#pragma unroll
            for (int r = 0; r < 4; ++r) acc[mi][nf][r] = 0.f;

    gemm_mainloop(cx, sb, tid, lane, wm, wn, MD / KC, acc);

    const int lr = lane >> 2;
    const int lc = (lane & 3) * 2;
#pragma unroll
    for (int mi = 0; mi < 4; ++mi) {
        const int row0 = bm * 128 + wm * 64 + mi * 16 + lr;
#pragma unroll
        for (int nf = 0; nf < 8; ++nf) {
            const int col = bn * 256 + wn * 64 + nf * 8 + lc;
            float* d = acc[mi][nf];
            const float bb0 = bias[col], bb1 = bias[col + 1];
            *(uint32_t*)(Ch + (size_t)row0 * HD + col) =
                pack_h2(__float2half_rn(d[0] + bb0), __float2half_rn(d[1] + bb1));
            *(uint32_t*)(Ch + (size_t)(row0 + 8) * HD + col) =
                pack_h2(__float2half_rn(d[2] + bb0), __float2half_rn(d[3] + bb1));
        }
    }
}

// ---------------------------------------------------------------------------
// Scores GEMM: C = alpha*(A*B^T), causal tile skip, fp32 out.
// ---------------------------------------------------------------------------
__global__ void __launch_bounds__(256, 1)
gemm_sc(const __half* __restrict__ A, const __half* __restrict__ B,
        float* __restrict__ Cf, float alpha)
{
    const int bm = blockIdx.y, bn = blockIdx.x, bz = blockIdx.z;
    if (2 * bn > bm) return;

    extern __shared__ char smem[];
    const uint32_t sb = smem_u32(smem);
    const int tid = threadIdx.x, lane = tid & 31, wid = tid >> 5;
    const int wm = wid >> 2, wn = wid & 3;

    GemmCtx cx;
    cx.gA = (const char*)(A + (size_t)bz * SS * HD + (size_t)(bm * 128) * HD);
    cx.gB = (const char*)(B + (size_t)bz * SS * HD + (size_t)(bn * 256) * HD);
    cx.ldaB = (size_t)HD * 2;
    cx.ldbB = (size_t)HD * 2;

    float acc[4][8][4];
#pragma unroll
    for (int mi = 0; mi < 4; ++mi)
#pragma unroll
        for (int nf = 0; nf < 8; ++nf)
#pragma unroll
            for (int r = 0; r < 4; ++r) acc[mi][nf][r] = 0.f;

    gemm_mainloop(cx, sb, tid, lane, wm, wn, HD / KC, acc);

    const int lr = lane >> 2;
    const int lc = (lane & 3) * 2;
    float* cp = Cf + (size_t)bz * SS * SS;
#pragma unroll
    for (int mi = 0; mi < 4; ++mi) {
        const int row0 = bm * 128 + wm * 64 + mi * 16 + lr;
#pragma unroll
        for (int nf = 0; nf < 8; ++nf) {
            const int col = bn * 256 + wn * 64 + nf * 8 + lc;
            float* d = acc[mi][nf];
            float2 o0 = { d[0] * alpha, d[1] * alpha };
            float2 o1 = { d[2] * alpha, d[3] * alpha };
            *(float2*)(cp + (size_t)row0 * SS + col) = o0;
            *(float2*)(cp + (size_t)(row0 + 8) * SS + col) = o1;
        }
    }
}

// ---------------------------------------------------------------------------
// PV GEMM: OUT = P @ VT^T, k-chunks limited by causality.
// bm reversed so longest CTAs are scheduled first (less wave-tail imbalance).
// ---------------------------------------------------------------------------
__global__ void __launch_bounds__(256, 1)
gemm_pv(const __half* __restrict__ A, const __half* __restrict__ B,
        float* __restrict__ Cf)
{
    const int bm = (int)gridDim.y - 1 - blockIdx.y;   // longest first
    const int bn = blockIdx.x, bz = blockIdx.z;
    const int nkt = (bm + 1) * 2;

    extern __shared__ char smem[];
    const uint32_t sb = smem_u32(smem);
    const int tid = threadIdx.x, lane = tid & 31, wid = tid >> 5;
    const int wm = wid >> 2, wn = wid & 3;

    GemmCtx cx;
    cx.gA = (const char*)(A + (size_t)bz * SS * SS + (size_t)(bm * 128) * SS);
    cx.gB = (const char*)(B + (size_t)bz * HD * SS + (size_t)(bn * 256) * SS);
    cx.ldaB = (size_t)SS * 2;
    cx.ldbB = (size_t)SS * 2;

    float acc[4][8][4];
#pragma unroll
    for (int mi = 0; mi < 4; ++mi)
#pragma unroll
        for (int nf = 0; nf < 8; ++nf)
#pragma unroll
            for (int r = 0; r < 4; ++r) acc[mi][nf][r] = 0.f;

    gemm_mainloop(cx, sb, tid, lane, wm, wn, nkt, acc);

    const int lr = lane >> 2;
    const int lc = (lane & 3) * 2;
    float* cp = Cf + (size_t)bz * SS * HD;
#pragma unroll
    for (int mi = 0; mi < 4; ++mi) {
        const int row0 = bm * 128 + wm * 64 + mi * 16 + lr;
#pragma unroll
        for (int nf = 0; nf < 8; ++nf) {
            const int col = bn * 256 + wn * 64 + nf * 8 + lc;
            float* d = acc[mi][nf];
            float2 o0 = { d[0], d[1] };
            float2 o1 = { d[2], d[3] };
            *(float2*)(cp + (size_t)row0 * HD + col) = o0;
            *(float2*)(cp + (size_t)(row0 + 8) * HD + col) = o1;
        }
    }
}

// ---------------------------------------------------------------------------
// Fused convert: 6 tensors (q,k,v,Wq,Wk,Wv) -> fp16, selected by blockIdx.y
// ---------------------------------------------------------------------------
__global__ void __launch_bounds__(256)
convert_hi6(const float* __restrict__ s0, const float* __restrict__ s1,
            const float* __restrict__ s2, const float* __restrict__ s3,
            const float* __restrict__ s4, const float* __restrict__ s5,
            __half* __restrict__ h0, __half* __restrict__ h1,
            __half* __restrict__ h2, __half* __restrict__ h3,
            __half* __restrict__ h4, __half* __restrict__ h5,
            size_t nX4, size_t nW4)
{
    const int t = blockIdx.y;
    const size_t n4 = (t < 3) ? nX4 : nW4;
    size_t i = (size_t)blockIdx.x * blockDim.x + threadIdx.x;
    if (i >= n4) return;
    const float* src = (t == 0) ? s0 : (t == 1) ? s1 : (t == 2) ? s2
                     : (t == 3) ? s3 : (t == 4) ? s4 : s5;
    __half* hi = (t == 0) ? h0 : (t == 1) ? h1 : (t == 2) ? h2
               : (t == 3) ? h3 : (t == 4) ? h4 : h5;
    float4 x = ((const float4*)src)[i];
    union { __half h[4]; uint2 u; } H;
    H.h[0] = __float2half_rn(x.x);
    H.h[1] = __float2half_rn(x.y);
    H.h[2] = __float2half_rn(x.z);
    H.h[3] = __float2half_rn(x.w);
    ((uint2*)hi)[i] = H.u;
}

// ---------------------------------------------------------------------------
// fp16 transpose per batch: src [B*S, H] -> dst [B][H][S]
// ---------------------------------------------------------------------------
__global__ void __launch_bounds__(256)
transpose_h(const __half* __restrict__ src, __half* __restrict__ dst)
{
    __shared__ __half t[32][33];
    const int b = blockIdx.z;
    const int h0 = blockIdx.x * 32, s0 = blockIdx.y * 32;
    const int tx = threadIdx.x, ty = threadIdx.y;  // 32 x 8
#pragma unroll
    for (int i = 0; i < 4; ++i)
        t[ty + i * 8][tx] = src[((size_t)b * SS + s0 + ty + i * 8) * HD + h0 + tx];
    __syncthreads();
#pragma unroll
    for (int i = 0; i < 4; ++i)
        dst[((size_t)b * HD + h0 + ty + i * 8) * SS + s0 + tx] = t[tx][ty + i * 8];
}

// ---------------------------------------------------------------------------
// Masked causal softmax: SC fp32 -> P fp16, zero-filled to 128-boundary.
// Each thread owns 8 contiguous elements (float4-vectorized).
// ---------------------------------------------------------------------------
__global__ void __launch_bounds__(256)
softmax_rows(const int* __restrict__ mask, const float* __restrict__ SC,
             __half* __restrict__ Phi)
{
    const int b = blockIdx.y;
    const int i = blockIdx.x;
    const size_t rowoff = ((size_t)b * SS + i) * SS;
    const float* row = SC + rowoff;
    const int* mrow = mask + (size_t)b * SS;
    const int tid = threadIdx.x;
    const int nvalid = i + 1;
    const int nfill = ((i >> 7) + 1) << 7;
    const int j0 = tid * 8;

    float vals[8];
    float vmax = -INFINITY;
    if (j0 + 7 < nvalid) {          // fully valid: vector loads, no mask branch per lane
        float4 x0 = *(const float4*)(row + j0);
        float4 x1 = *(const float4*)(row + j0 + 4);
        int4 m0 = *(const int4*)(mrow + j0);
        int4 m1 = *(const int4*)(mrow + j0 + 4);
        vals[0] = m0.x ? x0.x : -1e9f; vals[1] = m0.y ? x0.y : -1e9f;
        vals[2] = m0.z ? x0.z : -1e9f; vals[3] = m0.w ? x0.w : -1e9f;
        vals[4] = m1.x ? x1.x : -1e9f; vals[5] = m1.y ? x1.y : -1e9f;
        vals[6] = m1.z ? x1.z : -1e9f; vals[7] = m1.w ? x1.w : -1e9f;
#pragma unroll
        for (int t = 0; t < 8; ++t) vmax = fmaxf(vmax, vals[t]);
    } else {
#pragma unroll
        for (int t = 0; t < 8; ++t) {
            int j = j0 + t;
            float s = -INFINITY;
            if (j < nvalid) {
                s = row[j];
                if (mrow[j] == 0) s = -1e9f;
            }
            vals[t] = s;
            vmax = fmaxf(vmax, s);
        }
    }

    __shared__ float red[8];
#pragma unroll
    for (int o = 16; o; o >>= 1) vmax = fmaxf(vmax, __shfl_xor_sync(~0u, vmax, o));
    if ((tid & 31) == 0) red[tid >> 5] = vmax;
    __syncthreads();
    if (tid < 32) {
        float x = (tid < 8) ? red[tid] : -INFINITY;
#pragma unroll
        for (int o = 4; o; o >>= 1) x = fmaxf(x, __shfl_xor_sync(~0u, x, o));
        if (tid == 0) red[0] = x;
    }
    __syncthreads();
    vmax = red[0];
    __syncthreads();

    float lsum = 0.f;
#pragma unroll
    for (int t = 0; t < 8; ++t) {
        float e = __expf(vals[t] - vmax);
        vals[t] = e;
        lsum += e;
    }
#pragma unroll
    for (int o = 16; o; o >>= 1) lsum += __shfl_xor_sync(~0u, lsum, o);
    if ((tid & 31) == 0) red[tid >> 5] = lsum;
    __syncthreads();
    if (tid < 32) {
        float x = (tid < 8) ? red[tid] : 0.f;
#pragma unroll
        for (int o = 4; o; o >>= 1) x += __shfl_xor_sync(~0u, x, o);
        if (tid == 0) red[0] = x;
    }
    __syncthreads();
    const float rinv = 1.0f / red[0];

    if (j0 < nfill) {
        union { __half h[8]; uint4 u; } P;
#pragma unroll
        for (int t = 0; t < 8; ++t)
            P.h[t] = __float2half_rn(vals[t] * rinv);   // 0 for j > i
        *(uint4*)(Phi + rowoff + j0) = P.u;
    }
}

// ---------------------------------------------------------------------------
extern "C" void kernel_launch(void* const* d_in, const int* in_sizes, int n_in,
                              void* d_out, int out_size)
{
    (void)in_sizes; (void)n_in; (void)out_size;

    const float* q    = (const float*)d_in[0];
    const float* k    = (const float*)d_in[1];
    const float* v    = (const float*)d_in[2];
    const int*   mask = (const int*)  d_in[3];
    const float* Wq   = (const float*)d_in[4];
    const float* bq   = (const float*)d_in[5];
    const float* Wk   = (const float*)d_in[6];
    const float* bk   = (const float*)d_in[7];
    const float* Wv   = (const float*)d_in[8];
    const float* bv   = (const float*)d_in[9];
    float* out = (float*)d_out;

    static bool init = false;
    static __half *Xqh, *Xkh, *Xvh, *Wqh, *Wkh, *Wvh;
    static __half *QHh, *KHh, *VHh, *VTh, *Ph;
    static float *SC;
    if (!init) {
        void* p;
        cudaGetSymbolAddress(&p, g_Xq_hi); Xqh = (__half*)p;
        cudaGetSymbolAddress(&p, g_Xk_hi); Xkh = (__half*)p;
        cudaGetSymbolAddress(&p, g_Xv_hi); Xvh = (__half*)p;
        cudaGetSymbolAddress(&p, g_Wq_hi); Wqh = (__half*)p;
        cudaGetSymbolAddress(&p, g_Wk_hi); Wkh = (__half*)p;
        cudaGetSymbolAddress(&p, g_Wv_hi); Wvh = (__half*)p;
        cudaGetSymbolAddress(&p, g_QH_hi); QHh = (__half*)p;
        cudaGetSymbolAddress(&p, g_KH_hi); KHh = (__half*)p;
        cudaGetSymbolAddress(&p, g_VH_hi); VHh = (__half*)p;
        cudaGetSymbolAddress(&p, g_VT_hi); VTh = (__half*)p;
        cudaGetSymbolAddress(&p, g_P_hi);  Ph  = (__half*)p;
        cudaGetSymbolAddress(&p, g_SC);    SC  = (float*)p;
        cudaFuncSetAttribute((const void*)gemm_proj3, cudaFuncAttributeMaxDynamicSharedMemorySize, SMEMSZ);
        cudaFuncSetAttribute((const void*)gemm_sc,    cudaFuncAttributeMaxDynamicSharedMemorySize, SMEMSZ);
        cudaFuncSetAttribute((const void*)gemm_pv,    cudaFuncAttributeMaxDynamicSharedMemorySize, SMEMSZ);
        init = true;
    }

    // 1) Convert all 6 inputs to fp16 in one launch
    const size_t nX4 = (size_t)NT * MD / 4;
    const size_t nW4 = (size_t)HD * MD / 4;
    convert_hi6<<<dim3((unsigned)((nX4 + 255) / 256), 6), 256>>>(
        q, k, v, Wq, Wk, Wv, Xqh, Xkh, Xvh, Wqh, Wkh, Wvh, nX4, nW4);

    // 2) All 3 projections in ONE launch (768 CTAs -> minimal wave tail)
    dim3 gproj(HD / 256, NT / 128, 3);
    gemm_proj3<<<gproj, 256, SMEMSZ>>>(Xqh, Xkh, Xvh, Wqh, Wkh, Wvh,
                                       bq, bk, bv, QHh, KHh, VHh);

    // 3) Transpose V to [B][H][S]
    dim3 gt(HD / 32, SS / 32, BB);
    transpose_h<<<gt, dim3(32, 8)>>>(VHh, VTh);

    // 4) Scores (1-pass, causal skip)
    dim3 gsc(SS / 256, SS / 128, BB);
    gemm_sc<<<gsc, 256, SMEMSZ>>>(QHh, KHh, SC, 1.0f / 32.0f);

    // 5) Softmax -> P fp16
    softmax_rows<<<dim3(SS, BB), 256>>>(mask, SC, Ph);

    // 6) OUT = P @ VT^T (longest-first CTA order)
    dim3 go(HD / 256, SS / 128, BB);
    gemm_pv<<<go, 256, SMEMSZ>>>(Ph, VTh, out);
}

// round 13
// speedup vs baseline: 2.1141x; 1.0372x over previous
#include <cuda_runtime.h>
#include <cuda_fp16.h>
#include <math.h>
#include <stdint.h>

// Problem dims (fixed)
#define BB 4
#define SS 2048
#define MD 1024
#define HD 1024
#define NT 8192   // BB*SS

// GEMM tiling: CTA 128x256, 8 warps (2x4) of 64x64, K-chunk 64, 1-pass fp16
#define KC 64
#define STG    49152          // A(16K) + B(32K)
#define NS     4              // pipeline stages
#define SMEMSZ (NS * STG)     // 192 KB

#define SWZ(o) ((o) ^ (((o) >> 3) & 0x70))

// ---------------------------------------------------------------------------
// Scratch (__device__ globals; allocation-free rule)
// ---------------------------------------------------------------------------
__device__ __align__(256) __half g_Xq_hi[(size_t)NT * MD];
__device__ __align__(256) __half g_Xk_hi[(size_t)NT * MD];
__device__ __align__(256) __half g_Xv_hi[(size_t)NT * MD];
__device__ __align__(256) __half g_Wq_hi[(size_t)HD * MD];
__device__ __align__(256) __half g_Wk_hi[(size_t)HD * MD];
__device__ __align__(256) __half g_Wv_hi[(size_t)HD * MD];
__device__ __align__(256) __half g_QH_hi[(size_t)NT * HD];
__device__ __align__(256) __half g_KH_hi[(size_t)NT * HD];
__device__ __align__(256) __half g_VT_hi[(size_t)BB * HD * SS];
__device__ __align__(256) float  g_SC[(size_t)BB * SS * SS];
__device__ __align__(256) __half g_P_hi[(size_t)BB * SS * SS];

// ---------------------------------------------------------------------------
__device__ __forceinline__ uint32_t smem_u32(const void* p) {
    uint32_t a;
    asm("{ .reg .u64 t; cvta.to.shared.u64 t, %1; cvt.u32.u64 %0, t; }"
        : "=r"(a) : "l"(p));
    return a;
}
#define CP16(dst, src) asm volatile("cp.async.cg.shared.global [%0], [%1], 16;" :: "r"(dst), "l"(src))
#define CP_COMMIT()    asm volatile("cp.async.commit_group;" ::: "memory")
#define CP_WAIT2()     asm volatile("cp.async.wait_group 2;" ::: "memory")

__device__ __forceinline__ void ldsm4(uint32_t r[4], uint32_t a) {
    asm volatile("ldmatrix.sync.aligned.m8n8.x4.shared.b16 {%0,%1,%2,%3}, [%4];"
                 : "=r"(r[0]), "=r"(r[1]), "=r"(r[2]), "=r"(r[3]) : "r"(a));
}
__device__ __forceinline__ void mma_f32(float d[4], const uint32_t a[4],
                                        uint32_t b0, uint32_t b1) {
    asm volatile(
        "mma.sync.aligned.m16n8k16.row.col.f32.f16.f16.f32 "
        "{%0,%1,%2,%3}, {%4,%5,%6,%7}, {%8,%9}, {%0,%1,%2,%3};"
        : "+f"(d[0]), "+f"(d[1]), "+f"(d[2]), "+f"(d[3])
        : "r"(a[0]), "r"(a[1]), "r"(a[2]), "r"(a[3]), "r"(b0), "r"(b1));
}

__device__ __forceinline__ uint32_t pack_h2(__half a, __half b) {
    union { __half2 v; uint32_t u; } t;
    t.v.x = a; t.v.y = b;
    return t.u;
}

// ---------------------------------------------------------------------------
// Shared GEMM mainloop body (1-pass fp16 NT): acc += A*B^T over nkt chunks.
// ---------------------------------------------------------------------------
struct GemmCtx {
    const char* gA;
    const char* gB;
    size_t ldaB, ldbB;
};

__device__ __forceinline__ void gemm_mainloop(
    const GemmCtx& cx, uint32_t sb, int tid, int lane, int wm, int wn,
    int nkt, float acc[4][8][4])
{
    auto load_chunk = [&](int c, int buf) {
        const uint32_t st = sb + buf * STG;
        const size_t cb = (size_t)c * 128;
#pragma unroll
        for (int i = 0; i < 4; ++i) {          // A: 128 rows x 128B
            const int idx = tid + i * 256;
            const int row = idx >> 3, seg = (idx & 7) * 16;
            CP16(st + SWZ(row * 128 + seg), cx.gA + (size_t)row * cx.ldaB + cb + seg);
        }
#pragma unroll
        for (int i = 0; i < 8; ++i) {          // B: 256 rows x 128B
            const int idx = tid + i * 256;
            const int row = idx >> 3, seg = (idx & 7) * 16;
            CP16(st + 16384 + SWZ(row * 128 + seg), cx.gB + (size_t)row * cx.ldbB + cb + seg);
        }
        CP_COMMIT();
    };

    const int lrow = lane & 15;
    const int lcb0 = (lane >> 4) * 16;
    const int arow = wm * 64 + lrow;
    const int brow = wn * 64 + lrow;

#pragma unroll
    for (int i = 0; i < NS - 1; ++i)
        if (i < nkt) load_chunk(i, i);
        else         CP_COMMIT();

    for (int c = 0; c < nkt; ++c) {
        CP_WAIT2();
        __syncthreads();
        if (c + NS - 1 < nkt) load_chunk(c + NS - 1, (c + NS - 1) % NS);
        else                  CP_COMMIT();   // keep wait-group count aligned

        const uint32_t st = sb + (c % NS) * STG;
#pragma unroll
        for (int kk = 0; kk < 4; ++kk) {
            const int cb = kk * 32 + lcb0;
            uint32_t a[4][4], bh[4][4];
#pragma unroll
            for (int mi = 0; mi < 4; ++mi)
                ldsm4(a[mi], st + SWZ((arow + mi * 16) * 128 + cb));
#pragma unroll
            for (int nj = 0; nj < 4; ++nj)
                ldsm4(bh[nj], st + 16384 + SWZ((brow + nj * 16) * 128 + cb));
#pragma unroll
            for (int mi = 0; mi < 4; ++mi)
#pragma unroll
                for (int nj = 0; nj < 4; ++nj) {
                    mma_f32(acc[mi][nj * 2 + 0], a[mi], bh[nj][0], bh[nj][2]);
                    mma_f32(acc[mi][nj * 2 + 1], a[mi], bh[nj][1], bh[nj][3]);
                }
        }
    }
}

// ---------------------------------------------------------------------------
// Fused projection GEMM: grid.z in {0,1,2} selects q/k/v.
// t==0/1: write QH/KH row-major [NT, HD].
// t==2:   write VT transposed [B][H][S] directly (smem-staged, coalesced).
// ---------------------------------------------------------------------------
__global__ void __launch_bounds__(256, 1)
gemm_proj3(const __half* __restrict__ A0, const __half* __restrict__ A1,
           const __half* __restrict__ A2,
           const __half* __restrict__ B0, const __half* __restrict__ B1,
           const __half* __restrict__ B2,
           const float* __restrict__ b0p, const float* __restrict__ b1p,
           const float* __restrict__ b2p,
           __half* __restrict__ C0, __half* __restrict__ C1,
           __half* __restrict__ VT)
{
    const int bm = blockIdx.y, bn = blockIdx.x, t = blockIdx.z;
    const __half* A   = (t == 0) ? A0 : (t == 1) ? A1 : A2;
    const __half* B   = (t == 0) ? B0 : (t == 1) ? B1 : B2;
    const float* bias = (t == 0) ? b0p : (t == 1) ? b1p : b2p;

    extern __shared__ char smem[];
    const uint32_t sb = smem_u32(smem);
    const int tid = threadIdx.x, lane = tid & 31, wid = tid >> 5;
    const int wm = wid >> 2, wn = wid & 3;

    GemmCtx cx;
    cx.gA = (const char*)(A + (size_t)(bm * 128) * MD);
    cx.gB = (const char*)(B + (size_t)(bn * 256) * MD);
    cx.ldaB = (size_t)MD * 2;
    cx.ldbB = (size_t)MD * 2;

    float acc[4][8][4];
#pragma unroll
    for (int mi = 0; mi < 4; ++mi)
#pragma unroll
        for (int nf = 0; nf < 8; ++nf)
#pragma unroll
            for (int r = 0; r < 4; ++r) acc[mi][nf][r] = 0.f;

    gemm_mainloop(cx, sb, tid, lane, wm, wn, MD / KC, acc);

    const int lr = lane >> 2;
    const int lc = (lane & 3) * 2;

    if (t < 2) {
        __half* Ch = (t == 0) ? C0 : C1;
#pragma unroll
        for (int mi = 0; mi < 4; ++mi) {
            const int row0 = bm * 128 + wm * 64 + mi * 16 + lr;
#pragma unroll
            for (int nf = 0; nf < 8; ++nf) {
                const int col = bn * 256 + wn * 64 + nf * 8 + lc;
                float* d = acc[mi][nf];
                const float bb0 = bias[col], bb1 = bias[col + 1];
                *(uint32_t*)(Ch + (size_t)row0 * HD + col) =
                    pack_h2(__float2half_rn(d[0] + bb0), __float2half_rn(d[1] + bb1));
                *(uint32_t*)(Ch + (size_t)(row0 + 8) * HD + col) =
                    pack_h2(__float2half_rn(d[2] + bb0), __float2half_rn(d[3] + bb1));
            }
        }
    } else {
        // V: transpose tile through smem -> VT[b][h][s] coalesced
        // tile: 256 h-rows x 128 s-halfs; global row = bm*128+s
        __syncthreads();   // pipeline smem no longer in use after this
        constexpr int TP = 136;                 // padded row (halfs)
        __half* ts = (__half*)smem;             // [256][TP] = 69632 B
#pragma unroll
        for (int mi = 0; mi < 4; ++mi) {
            const int sl0 = wm * 64 + mi * 16 + lr;
#pragma unroll
            for (int nf = 0; nf < 8; ++nf) {
                const int hl = wn * 64 + nf * 8 + lc;
                float* d = acc[mi][nf];
                const float bb0 = bias[bn * 256 + hl], bb1 = bias[bn * 256 + hl + 1];
                ts[(hl + 0) * TP + sl0]     = __float2half_rn(d[0] + bb0);
                ts[(hl + 1) * TP + sl0]     = __float2half_rn(d[1] + bb1);
                ts[(hl + 0) * TP + sl0 + 8] = __float2half_rn(d[2] + bb0);
                ts[(hl + 1) * TP + sl0 + 8] = __float2half_rn(d[3] + bb1);
            }
        }
        __syncthreads();
        // write out: 256 h-rows x 128 halfs = 4096 uint4 units, 16 iters x 256 thr
        const int grow = bm * 128;              // global token row of tile start
        const int b    = grow >> 11;            // SS = 2048
        const int s0   = grow & 2047;
        __half* dst = VT + (size_t)b * HD * SS + s0;
#pragma unroll
        for (int it = 0; it < 16; ++it) {
            const int idx = tid + it * 256;
            const int hl = idx >> 4, seg = (idx & 15) * 8;
            *(uint4*)(dst + (size_t)(bn * 256 + hl) * SS + seg) =
                *(const uint4*)&ts[hl * TP + seg];
        }
    }
}

// ---------------------------------------------------------------------------
// Scores GEMM: C = alpha*(A*B^T), causal tile skip, fp32 out.
// ---------------------------------------------------------------------------
__global__ void __launch_bounds__(256, 1)
gemm_sc(const __half* __restrict__ A, const __half* __restrict__ B,
        float* __restrict__ Cf, float alpha)
{
    const int bm = blockIdx.y, bn = blockIdx.x, bz = blockIdx.z;
    if (2 * bn > bm) return;

    extern __shared__ char smem[];
    const uint32_t sb = smem_u32(smem);
    const int tid = threadIdx.x, lane = tid & 31, wid = tid >> 5;
    const int wm = wid >> 2, wn = wid & 3;

    GemmCtx cx;
    cx.gA = (const char*)(A + (size_t)bz * SS * HD + (size_t)(bm * 128) * HD);
    cx.gB = (const char*)(B + (size_t)bz * SS * HD + (size_t)(bn * 256) * HD);
    cx.ldaB = (size_t)HD * 2;
    cx.ldbB = (size_t)HD * 2;

    float acc[4][8][4];
#pragma unroll
    for (int mi = 0; mi < 4; ++mi)
#pragma unroll
        for (int nf = 0; nf < 8; ++nf)
#pragma unroll
            for (int r = 0; r < 4; ++r) acc[mi][nf][r] = 0.f;

    gemm_mainloop(cx, sb, tid, lane, wm, wn, HD / KC, acc);

    const int lr = lane >> 2;
    const int lc = (lane & 3) * 2;
    float* cp = Cf + (size_t)bz * SS * SS;
#pragma unroll
    for (int mi = 0; mi < 4; ++mi) {
        const int row0 = bm * 128 + wm * 64 + mi * 16 + lr;
#pragma unroll
        for (int nf = 0; nf < 8; ++nf) {
            const int col = bn * 256 + wn * 64 + nf * 8 + lc;
            float* d = acc[mi][nf];
            float2 o0 = { d[0] * alpha, d[1] * alpha };
            float2 o1 = { d[2] * alpha, d[3] * alpha };
            *(float2*)(cp + (size_t)row0 * SS + col) = o0;
            *(float2*)(cp + (size_t)(row0 + 8) * SS + col) = o1;
        }
    }
}

// ---------------------------------------------------------------------------
// PV GEMM: OUT = P @ VT^T, k-chunks limited by causality, longest-first.
// ---------------------------------------------------------------------------
__global__ void __launch_bounds__(256, 1)
gemm_pv(const __half* __restrict__ A, const __half* __restrict__ B,
        float* __restrict__ Cf)
{
    const int bm = (int)gridDim.y - 1 - blockIdx.y;   // longest first
    const int bn = blockIdx.x, bz = blockIdx.z;
    const int nkt = (bm + 1) * 2;

    extern __shared__ char smem[];
    const uint32_t sb = smem_u32(smem);
    const int tid = threadIdx.x, lane = tid & 31, wid = tid >> 5;
    const int wm = wid >> 2, wn = wid & 3;

    GemmCtx cx;
    cx.gA = (const char*)(A + (size_t)bz * SS * SS + (size_t)(bm * 128) * SS);
    cx.gB = (const char*)(B + (size_t)bz * HD * SS + (size_t)(bn * 256) * SS);
    cx.ldaB = (size_t)SS * 2;
    cx.ldbB = (size_t)SS * 2;

    float acc[4][8][4];
#pragma unroll
    for (int mi = 0; mi < 4; ++mi)
#pragma unroll
        for (int nf = 0; nf < 8; ++nf)
#pragma unroll
            for (int r = 0; r < 4; ++r) acc[mi][nf][r] = 0.f;

    gemm_mainloop(cx, sb, tid, lane, wm, wn, nkt, acc);

    const int lr = lane >> 2;
    const int lc = (lane & 3) * 2;
    float* cp = Cf + (size_t)bz * SS * HD;
#pragma unroll
    for (int mi = 0; mi < 4; ++mi) {
        const int row0 = bm * 128 + wm * 64 + mi * 16 + lr;
#pragma unroll
        for (int nf = 0; nf < 8; ++nf) {
            const int col = bn * 256 + wn * 64 + nf * 8 + lc;
            float* d = acc[mi][nf];
            float2 o0 = { d[0], d[1] };
            float2 o1 = { d[2], d[3] };
            *(float2*)(cp + (size_t)row0 * HD + col) = o0;
            *(float2*)(cp + (size_t)(row0 + 8) * HD + col) = o1;
        }
    }
}

// ---------------------------------------------------------------------------
// Fused convert: 6 tensors -> fp16, 4x float4 per thread (MLP=4).
// ---------------------------------------------------------------------------
__global__ void __launch_bounds__(256)
convert_hi6(const float* __restrict__ s0, const float* __restrict__ s1,
            const float* __restrict__ s2, const float* __restrict__ s3,
            const float* __restrict__ s4, const float* __restrict__ s5,
            __half* __restrict__ h0, __half* __restrict__ h1,
            __half* __restrict__ h2, __half* __restrict__ h3,
            __half* __restrict__ h4, __half* __restrict__ h5,
            size_t nX4, size_t nW4)
{
    const int t = blockIdx.y;
    const size_t n4 = (t < 3) ? nX4 : nW4;
    const size_t i0 = ((size_t)blockIdx.x * blockDim.x + threadIdx.x) * 4;
    if (i0 >= n4) return;   // n4 is a multiple of 4
    const float* src = (t == 0) ? s0 : (t == 1) ? s1 : (t == 2) ? s2
                     : (t == 3) ? s3 : (t == 4) ? s4 : s5;
    __half* hi = (t == 0) ? h0 : (t == 1) ? h1 : (t == 2) ? h2
               : (t == 3) ? h3 : (t == 4) ? h4 : h5;
    float4 x[4];
#pragma unroll
    for (int u = 0; u < 4; ++u) x[u] = ((const float4*)src)[i0 + u];
#pragma unroll
    for (int u = 0; u < 4; ++u) {
        union { __half h[4]; uint2 v; } H;
        H.h[0] = __float2half_rn(x[u].x);
        H.h[1] = __float2half_rn(x[u].y);
        H.h[2] = __float2half_rn(x[u].z);
        H.h[3] = __float2half_rn(x[u].w);
        ((uint2*)hi)[i0 + u] = H.v;
    }
}

// ---------------------------------------------------------------------------
// Masked causal softmax: SC fp32 -> P fp16, zero-filled to 128-boundary.
// ---------------------------------------------------------------------------
__global__ void __launch_bounds__(256)
softmax_rows(const int* __restrict__ mask, const float* __restrict__ SC,
             __half* __restrict__ Phi)
{
    const int b = blockIdx.y;
    const int i = blockIdx.x;
    const size_t rowoff = ((size_t)b * SS + i) * SS;
    const float* row = SC + rowoff;
    const int* mrow = mask + (size_t)b * SS;
    const int tid = threadIdx.x;
    const int nvalid = i + 1;
    const int nfill = ((i >> 7) + 1) << 7;
    const int j0 = tid * 8;

    float vals[8];
    float vmax = -INFINITY;
    if (j0 + 7 < nvalid) {
        float4 x0 = *(const float4*)(row + j0);
        float4 x1 = *(const float4*)(row + j0 + 4);
        int4 m0 = *(const int4*)(mrow + j0);
        int4 m1 = *(const int4*)(mrow + j0 + 4);
        vals[0] = m0.x ? x0.x : -1e9f; vals[1] = m0.y ? x0.y : -1e9f;
        vals[2] = m0.z ? x0.z : -1e9f; vals[3] = m0.w ? x0.w : -1e9f;
        vals[4] = m1.x ? x1.x : -1e9f; vals[5] = m1.y ? x1.y : -1e9f;
        vals[6] = m1.z ? x1.z : -1e9f; vals[7] = m1.w ? x1.w : -1e9f;
#pragma unroll
        for (int t = 0; t < 8; ++t) vmax = fmaxf(vmax, vals[t]);
    } else {
#pragma unroll
        for (int t = 0; t < 8; ++t) {
            int j = j0 + t;
            float s = -INFINITY;
            if (j < nvalid) {
                s = row[j];
                if (mrow[j] == 0) s = -1e9f;
            }
            vals[t] = s;
            vmax = fmaxf(vmax, s);
        }
    }

    __shared__ float red[8];
#pragma unroll
    for (int o = 16; o; o >>= 1) vmax = fmaxf(vmax, __shfl_xor_sync(~0u, vmax, o));
    if ((tid & 31) == 0) red[tid >> 5] = vmax;
    __syncthreads();
    if (tid < 32) {
        float x = (tid < 8) ? red[tid] : -INFINITY;
#pragma unroll
        for (int o = 4; o; o >>= 1) x = fmaxf(x, __shfl_xor_sync(~0u, x, o));
        if (tid == 0) red[0] = x;
    }
    __syncthreads();
    vmax = red[0];
    __syncthreads();

    float lsum = 0.f;
#pragma unroll
    for (int t = 0; t < 8; ++t) {
        float e = __expf(vals[t] - vmax);
        vals[t] = e;
        lsum += e;
    }
#pragma unroll
    for (int o = 16; o; o >>= 1) lsum += __shfl_xor_sync(~0u, lsum, o);
    if ((tid & 31) == 0) red[tid >> 5] = lsum;
    __syncthreads();
    if (tid < 32) {
        float x = (tid < 8) ? red[tid] : 0.f;
#pragma unroll
        for (int o = 4; o; o >>= 1) x += __shfl_xor_sync(~0u, x, o);
        if (tid == 0) red[0] = x;
    }
    __syncthreads();
    const float rinv = 1.0f / red[0];

    if (j0 < nfill) {
        union { __half h[8]; uint4 u; } P;
#pragma unroll
        for (int t = 0; t < 8; ++t)
            P.h[t] = __float2half_rn(vals[t] * rinv);   // 0 for j > i
        *(uint4*)(Phi + rowoff + j0) = P.u;
    }
}

// ---------------------------------------------------------------------------
extern "C" void kernel_launch(void* const* d_in, const int* in_sizes, int n_in,
                              void* d_out, int out_size)
{
    (void)in_sizes; (void)n_in; (void)out_size;

    const float* q    = (const float*)d_in[0];
    const float* k    = (const float*)d_in[1];
    const float* v    = (const float*)d_in[2];
    const int*   mask = (const int*)  d_in[3];
    const float* Wq   = (const float*)d_in[4];
    const float* bq   = (const float*)d_in[5];
    const float* Wk   = (const float*)d_in[6];
    const float* bk   = (const float*)d_in[7];
    const float* Wv   = (const float*)d_in[8];
    const float* bv   = (const float*)d_in[9];
    float* out = (float*)d_out;

    static bool init = false;
    static __half *Xqh, *Xkh, *Xvh, *Wqh, *Wkh, *Wvh;
    static __half *QHh, *KHh, *VTh, *Ph;
    static float *SC;
    if (!init) {
        void* p;
        cudaGetSymbolAddress(&p, g_Xq_hi); Xqh = (__half*)p;
        cudaGetSymbolAddress(&p, g_Xk_hi); Xkh = (__half*)p;
        cudaGetSymbolAddress(&p, g_Xv_hi); Xvh = (__half*)p;
        cudaGetSymbolAddress(&p, g_Wq_hi); Wqh = (__half*)p;
        cudaGetSymbolAddress(&p, g_Wk_hi); Wkh = (__half*)p;
        cudaGetSymbolAddress(&p, g_Wv_hi); Wvh = (__half*)p;
        cudaGetSymbolAddress(&p, g_QH_hi); QHh = (__half*)p;
        cudaGetSymbolAddress(&p, g_KH_hi); KHh = (__half*)p;
        cudaGetSymbolAddress(&p, g_VT_hi); VTh = (__half*)p;
        cudaGetSymbolAddress(&p, g_P_hi);  Ph  = (__half*)p;
        cudaGetSymbolAddress(&p, g_SC);    SC  = (float*)p;
        cudaFuncSetAttribute((const void*)gemm_proj3, cudaFuncAttributeMaxDynamicSharedMemorySize, SMEMSZ);
        cudaFuncSetAttribute((const void*)gemm_sc,    cudaFuncAttributeMaxDynamicSharedMemorySize, SMEMSZ);
        cudaFuncSetAttribute((const void*)gemm_pv,    cudaFuncAttributeMaxDynamicSharedMemorySize, SMEMSZ);
        init = true;
    }

    // 1) Convert all 6 inputs to fp16 in one launch (4x float4 per thread)
    const size_t nX4 = (size_t)NT * MD / 4;
    const size_t nW4 = (size_t)HD * MD / 4;
    convert_hi6<<<dim3((unsigned)((nX4 / 4 + 255) / 256), 6), 256>>>(
        q, k, v, Wq, Wk, Wv, Xqh, Xkh, Xvh, Wqh, Wkh, Wvh, nX4, nW4);

    // 2) All 3 projections in ONE launch; V writes VT directly
    dim3 gproj(HD / 256, NT / 128, 3);
    gemm_proj3<<<gproj, 256, SMEMSZ>>>(Xqh, Xkh, Xvh, Wqh, Wkh, Wvh,
                                       bq, bk, bv, QHh, KHh, VTh);

    // 3) Scores (1-pass, causal skip)
    dim3 gsc(SS / 256, SS / 128, BB);
    gemm_sc<<<gsc, 256, SMEMSZ>>>(QHh, KHh, SC, 1.0f / 32.0f);

    // 4) Softmax -> P fp16
    softmax_rows<<<dim3(SS, BB), 256>>>(mask, SC, Ph);

    // 5) OUT = P @ VT^T (longest-first CTA order)
    dim3 go(HD / 256, SS / 128, BB);
    gemm_pv<<<go, 256, SMEMSZ>>>(Ph, VTh, out);
}

// round 14
// speedup vs baseline: 2.2158x; 1.0481x over previous
#include <cuda_runtime.h>
#include <cuda_fp16.h>
#include <math.h>
#include <stdint.h>

// Problem dims (fixed)
#define BB 4
#define SS 2048
#define MD 1024
#define HD 1024
#define NT 8192   // BB*SS

// GEMM tiling: CTA 128x128, 8 warps (2x4) of 64x32, K-chunk 64, 1-pass fp16
// occupancy 2 CTAs/SM (decoupled pipelines)
#define KC 64
#define STG    32768          // A(16K) + B(16K)
#define NS     3              // pipeline stages
#define SMEMSZ (NS * STG)     // 96 KB -> 2 CTAs/SM

#define SWZ(o) ((o) ^ (((o) >> 3) & 0x70))

// ---------------------------------------------------------------------------
// Scratch (__device__ globals; allocation-free rule)
// ---------------------------------------------------------------------------
__device__ __align__(256) __half g_Xq_hi[(size_t)NT * MD];
__device__ __align__(256) __half g_Xk_hi[(size_t)NT * MD];
__device__ __align__(256) __half g_Xv_hi[(size_t)NT * MD];
__device__ __align__(256) __half g_Wq_hi[(size_t)HD * MD];
__device__ __align__(256) __half g_Wk_hi[(size_t)HD * MD];
__device__ __align__(256) __half g_Wv_hi[(size_t)HD * MD];
__device__ __align__(256) __half g_QH_hi[(size_t)NT * HD];
__device__ __align__(256) __half g_KH_hi[(size_t)NT * HD];
__device__ __align__(256) __half g_VT_hi[(size_t)BB * HD * SS];
__device__ __align__(256) float  g_SC[(size_t)BB * SS * SS];
__device__ __align__(256) __half g_P_hi[(size_t)BB * SS * SS];

// ---------------------------------------------------------------------------
__device__ __forceinline__ uint32_t smem_u32(const void* p) {
    uint32_t a;
    asm("{ .reg .u64 t; cvta.to.shared.u64 t, %1; cvt.u32.u64 %0, t; }"
        : "=r"(a) : "l"(p));
    return a;
}
#define CP16(dst, src) asm volatile("cp.async.cg.shared.global [%0], [%1], 16;" :: "r"(dst), "l"(src))
#define CP_COMMIT()    asm volatile("cp.async.commit_group;" ::: "memory")
#define CP_WAIT1()     asm volatile("cp.async.wait_group 1;" ::: "memory")

__device__ __forceinline__ void ldsm4(uint32_t r[4], uint32_t a) {
    asm volatile("ldmatrix.sync.aligned.m8n8.x4.shared.b16 {%0,%1,%2,%3}, [%4];"
                 : "=r"(r[0]), "=r"(r[1]), "=r"(r[2]), "=r"(r[3]) : "r"(a));
}
__device__ __forceinline__ void mma_f32(float d[4], const uint32_t a[4],
                                        uint32_t b0, uint32_t b1) {
    asm volatile(
        "mma.sync.aligned.m16n8k16.row.col.f32.f16.f16.f32 "
        "{%0,%1,%2,%3}, {%4,%5,%6,%7}, {%8,%9}, {%0,%1,%2,%3};"
        : "+f"(d[0]), "+f"(d[1]), "+f"(d[2]), "+f"(d[3])
        : "r"(a[0]), "r"(a[1]), "r"(a[2]), "r"(a[3]), "r"(b0), "r"(b1));
}

__device__ __forceinline__ uint32_t pack_h2(__half a, __half b) {
    union { __half2 v; uint32_t u; } t;
    t.v.x = a; t.v.y = b;
    return t.u;
}

// ---------------------------------------------------------------------------
// GEMM mainloop (1-pass fp16 NT), CTA tile 128x128, warp tile 64x32.
// ---------------------------------------------------------------------------
struct GemmCtx {
    const char* gA;
    const char* gB;
    size_t ldaB, ldbB;
};

__device__ __forceinline__ void gemm_mainloop(
    const GemmCtx& cx, uint32_t sb, int tid, int lane, int wm, int wn,
    int nkt, float acc[4][4][4])
{
    auto load_chunk = [&](int c, int buf) {
        const uint32_t st = sb + buf * STG;
        const size_t cb = (size_t)c * 128;
#pragma unroll
        for (int i = 0; i < 4; ++i) {          // A: 128 rows x 128B
            const int idx = tid + i * 256;
            const int row = idx >> 3, seg = (idx & 7) * 16;
            CP16(st + SWZ(row * 128 + seg), cx.gA + (size_t)row * cx.ldaB + cb + seg);
        }
#pragma unroll
        for (int i = 0; i < 4; ++i) {          // B: 128 rows x 128B
            const int idx = tid + i * 256;
            const int row = idx >> 3, seg = (idx & 7) * 16;
            CP16(st + 16384 + SWZ(row * 128 + seg), cx.gB + (size_t)row * cx.ldbB + cb + seg);
        }
        CP_COMMIT();
    };

    const int lrow = lane & 15;
    const int lcb0 = (lane >> 4) * 16;
    const int arow = wm * 64 + lrow;
    const int brow = wn * 32 + lrow;

#pragma unroll
    for (int i = 0; i < NS - 1; ++i)
        if (i < nkt) load_chunk(i, i);
        else         CP_COMMIT();

    for (int c = 0; c < nkt; ++c) {
        CP_WAIT1();
        __syncthreads();
        if (c + NS - 1 < nkt) load_chunk(c + NS - 1, (c + NS - 1) % NS);
        else                  CP_COMMIT();   // keep wait-group count aligned

        const uint32_t st = sb + (c % NS) * STG;
#pragma unroll
        for (int kk = 0; kk < 4; ++kk) {
            const int cb = kk * 32 + lcb0;
            uint32_t a[4][4], bh[2][4];
#pragma unroll
            for (int mi = 0; mi < 4; ++mi)
                ldsm4(a[mi], st + SWZ((arow + mi * 16) * 128 + cb));
#pragma unroll
            for (int nj = 0; nj < 2; ++nj)
                ldsm4(bh[nj], st + 16384 + SWZ((brow + nj * 16) * 128 + cb));
#pragma unroll
            for (int mi = 0; mi < 4; ++mi)
#pragma unroll
                for (int nj = 0; nj < 2; ++nj) {
                    mma_f32(acc[mi][nj * 2 + 0], a[mi], bh[nj][0], bh[nj][2]);
                    mma_f32(acc[mi][nj * 2 + 1], a[mi], bh[nj][1], bh[nj][3]);
                }
        }
    }
}

// ---------------------------------------------------------------------------
// Fused projection GEMM: grid.z selects q/k/v; V writes VT directly.
// ---------------------------------------------------------------------------
__global__ void __launch_bounds__(256, 2)
gemm_proj3(const __half* __restrict__ A0, const __half* __restrict__ A1,
           const __half* __restrict__ A2,
           const __half* __restrict__ B0, const __half* __restrict__ B1,
           const __half* __restrict__ B2,
           const float* __restrict__ b0p, const float* __restrict__ b1p,
           const float* __restrict__ b2p,
           __half* __restrict__ C0, __half* __restrict__ C1,
           __half* __restrict__ VT)
{
    const int bm = blockIdx.y, bn = blockIdx.x, t = blockIdx.z;
    const __half* A   = (t == 0) ? A0 : (t == 1) ? A1 : A2;
    const __half* B   = (t == 0) ? B0 : (t == 1) ? B1 : B2;
    const float* bias = (t == 0) ? b0p : (t == 1) ? b1p : b2p;

    extern __shared__ char smem[];
    const uint32_t sb = smem_u32(smem);
    const int tid = threadIdx.x, lane = tid & 31, wid = tid >> 5;
    const int wm = wid >> 2, wn = wid & 3;

    GemmCtx cx;
    cx.gA = (const char*)(A + (size_t)(bm * 128) * MD);
    cx.gB = (const char*)(B + (size_t)(bn * 128) * MD);
    cx.ldaB = (size_t)MD * 2;
    cx.ldbB = (size_t)MD * 2;

    float acc[4][4][4];
#pragma unroll
    for (int mi = 0; mi < 4; ++mi)
#pragma unroll
        for (int nf = 0; nf < 4; ++nf)
#pragma unroll
            for (int r = 0; r < 4; ++r) acc[mi][nf][r] = 0.f;

    gemm_mainloop(cx, sb, tid, lane, wm, wn, MD / KC, acc);

    const int lr = lane >> 2;
    const int lc = (lane & 3) * 2;

    if (t < 2) {
        __half* Ch = (t == 0) ? C0 : C1;
#pragma unroll
        for (int mi = 0; mi < 4; ++mi) {
            const int row0 = bm * 128 + wm * 64 + mi * 16 + lr;
#pragma unroll
            for (int nf = 0; nf < 4; ++nf) {
                const int col = bn * 128 + wn * 32 + nf * 8 + lc;
                float* d = acc[mi][nf];
                const float bb0 = bias[col], bb1 = bias[col + 1];
                *(uint32_t*)(Ch + (size_t)row0 * HD + col) =
                    pack_h2(__float2half_rn(d[0] + bb0), __float2half_rn(d[1] + bb1));
                *(uint32_t*)(Ch + (size_t)(row0 + 8) * HD + col) =
                    pack_h2(__float2half_rn(d[2] + bb0), __float2half_rn(d[3] + bb1));
            }
        }
    } else {
        // V: transpose tile through smem -> VT[b][h][s] coalesced
        // tile: 128 h-rows x 128 s-halfs; global row = bm*128+s
        __syncthreads();   // pipeline smem no longer in use
        constexpr int TP = 136;                 // padded row (halfs)
        __half* ts = (__half*)smem;             // [128][TP] = 34816 B
#pragma unroll
        for (int mi = 0; mi < 4; ++mi) {
            const int sl0 = wm * 64 + mi * 16 + lr;
#pragma unroll
            for (int nf = 0; nf < 4; ++nf) {
                const int hl = wn * 32 + nf * 8 + lc;
                float* d = acc[mi][nf];
                const float bb0 = bias[bn * 128 + hl], bb1 = bias[bn * 128 + hl + 1];
                ts[(hl + 0) * TP + sl0]     = __float2half_rn(d[0] + bb0);
                ts[(hl + 1) * TP + sl0]     = __float2half_rn(d[1] + bb1);
                ts[(hl + 0) * TP + sl0 + 8] = __float2half_rn(d[2] + bb0);
                ts[(hl + 1) * TP + sl0 + 8] = __float2half_rn(d[3] + bb1);
            }
        }
        __syncthreads();
        // write out: 128 h-rows x 128 halfs = 2048 uint4 units, 8 iters x 256 thr
        const int grow = bm * 128;
        const int b    = grow >> 11;            // SS = 2048
        const int s0   = grow & 2047;
        __half* dst = VT + (size_t)b * HD * SS + s0;
#pragma unroll
        for (int it = 0; it < 8; ++it) {
            const int idx = tid + it * 256;
            const int hl = idx >> 4, seg = (idx & 15) * 8;
            *(uint4*)(dst + (size_t)(bn * 128 + hl) * SS + seg) =
                *(const uint4*)&ts[hl * TP + seg];
        }
    }
}

// ---------------------------------------------------------------------------
// Scores GEMM: C = alpha*(A*B^T), causal tile skip (bn > bm), fp32 out.
// ---------------------------------------------------------------------------
__global__ void __launch_bounds__(256, 2)
gemm_sc(const __half* __restrict__ A, const __half* __restrict__ B,
        float* __restrict__ Cf, float alpha)
{
    const int bm = blockIdx.y, bn = blockIdx.x, bz = blockIdx.z;
    if (bn > bm) return;

    extern __shared__ char smem[];
    const uint32_t sb = smem_u32(smem);
    const int tid = threadIdx.x, lane = tid & 31, wid = tid >> 5;
    const int wm = wid >> 2, wn = wid & 3;

    GemmCtx cx;
    cx.gA = (const char*)(A + (size_t)bz * SS * HD + (size_t)(bm * 128) * HD);
    cx.gB = (const char*)(B + (size_t)bz * SS * HD + (size_t)(bn * 128) * HD);
    cx.ldaB = (size_t)HD * 2;
    cx.ldbB = (size_t)HD * 2;

    float acc[4][4][4];
#pragma unroll
    for (int mi = 0; mi < 4; ++mi)
#pragma unroll
        for (int nf = 0; nf < 4; ++nf)
#pragma unroll
            for (int r = 0; r < 4; ++r) acc[mi][nf][r] = 0.f;

    gemm_mainloop(cx, sb, tid, lane, wm, wn, HD / KC, acc);

    const int lr = lane >> 2;
    const int lc = (lane & 3) * 2;
    float* cp = Cf + (size_t)bz * SS * SS;
#pragma unroll
    for (int mi = 0; mi < 4; ++mi) {
        const int row0 = bm * 128 + wm * 64 + mi * 16 + lr;
#pragma unroll
        for (int nf = 0; nf < 4; ++nf) {
            const int col = bn * 128 + wn * 32 + nf * 8 + lc;
            float* d = acc[mi][nf];
            float2 o0 = { d[0] * alpha, d[1] * alpha };
            float2 o1 = { d[2] * alpha, d[3] * alpha };
            *(float2*)(cp + (size_t)row0 * SS + col) = o0;
            *(float2*)(cp + (size_t)(row0 + 8) * SS + col) = o1;
        }
    }
}

// ---------------------------------------------------------------------------
// PV GEMM: OUT = P @ VT^T, k-chunks limited by causality, longest-first.
// ---------------------------------------------------------------------------
__global__ void __launch_bounds__(256, 2)
gemm_pv(const __half* __restrict__ A, const __half* __restrict__ B,
        float* __restrict__ Cf)
{
    const int bm = (int)gridDim.y - 1 - blockIdx.y;   // longest first
    const int bn = blockIdx.x, bz = blockIdx.z;
    const int nkt = (bm + 1) * 2;

    extern __shared__ char smem[];
    const uint32_t sb = smem_u32(smem);
    const int tid = threadIdx.x, lane = tid & 31, wid = tid >> 5;
    const int wm = wid >> 2, wn = wid & 3;

    GemmCtx cx;
    cx.gA = (const char*)(A + (size_t)bz * SS * SS + (size_t)(bm * 128) * SS);
    cx.gB = (const char*)(B + (size_t)bz * HD * SS + (size_t)(bn * 128) * SS);
    cx.ldaB = (size_t)SS * 2;
    cx.ldbB = (size_t)SS * 2;

    float acc[4][4][4];
#pragma unroll
    for (int mi = 0; mi < 4; ++mi)
#pragma unroll
        for (int nf = 0; nf < 4; ++nf)
#pragma unroll
            for (int r = 0; r < 4; ++r) acc[mi][nf][r] = 0.f;

    gemm_mainloop(cx, sb, tid, lane, wm, wn, nkt, acc);

    const int lr = lane >> 2;
    const int lc = (lane & 3) * 2;
    float* cp = Cf + (size_t)bz * SS * HD;
#pragma unroll
    for (int mi = 0; mi < 4; ++mi) {
        const int row0 = bm * 128 + wm * 64 + mi * 16 + lr;
#pragma unroll
        for (int nf = 0; nf < 4; ++nf) {
            const int col = bn * 128 + wn * 32 + nf * 8 + lc;
            float* d = acc[mi][nf];
            float2 o0 = { d[0], d[1] };
            float2 o1 = { d[2], d[3] };
            *(float2*)(cp + (size_t)row0 * HD + col) = o0;
            *(float2*)(cp + (size_t)(row0 + 8) * HD + col) = o1;
        }
    }
}

// ---------------------------------------------------------------------------
// Fused convert: 6 tensors -> fp16, 4x float4 per thread (MLP=4).
// ---------------------------------------------------------------------------
__global__ void __launch_bounds__(256)
convert_hi6(const float* __restrict__ s0, const float* __restrict__ s1,
            const float* __restrict__ s2, const float* __restrict__ s3,
            const float* __restrict__ s4, const float* __restrict__ s5,
            __half* __restrict__ h0, __half* __restrict__ h1,
            __half* __restrict__ h2, __half* __restrict__ h3,
            __half* __restrict__ h4, __half* __restrict__ h5,
            size_t nX4, size_t nW4)
{
    const int t = blockIdx.y;
    const size_t n4 = (t < 3) ? nX4 : nW4;
    const size_t i0 = ((size_t)blockIdx.x * blockDim.x + threadIdx.x) * 4;
    if (i0 >= n4) return;   // n4 is a multiple of 4
    const float* src = (t == 0) ? s0 : (t == 1) ? s1 : (t == 2) ? s2
                     : (t == 3) ? s3 : (t == 4) ? s4 : s5;
    __half* hi = (t == 0) ? h0 : (t == 1) ? h1 : (t == 2) ? h2
               : (t == 3) ? h3 : (t == 4) ? h4 : h5;
    float4 x[4];
#pragma unroll
    for (int u = 0; u < 4; ++u) x[u] = ((const float4*)src)[i0 + u];
#pragma unroll
    for (int u = 0; u < 4; ++u) {
        union { __half h[4]; uint2 v; } H;
        H.h[0] = __float2half_rn(x[u].x);
        H.h[1] = __float2half_rn(x[u].y);
        H.h[2] = __float2half_rn(x[u].z);
        H.h[3] = __float2half_rn(x[u].w);
        ((uint2*)hi)[i0 + u] = H.v;
    }
}

// ---------------------------------------------------------------------------
// Masked causal softmax: SC fp32 -> P fp16, zero-filled to 128-boundary.
// ---------------------------------------------------------------------------
__global__ void __launch_bounds__(256)
softmax_rows(const int* __restrict__ mask, const float* __restrict__ SC,
             __half* __restrict__ Phi)
{
    const int b = blockIdx.y;
    const int i = blockIdx.x;
    const size_t rowoff = ((size_t)b * SS + i) * SS;
    const float* row = SC + rowoff;
    const int* mrow = mask + (size_t)b * SS;
    const int tid = threadIdx.x;
    const int nvalid = i + 1;
    const int nfill = ((i >> 7) + 1) << 7;
    const int j0 = tid * 8;

    float vals[8];
    float vmax = -INFINITY;
    if (j0 + 7 < nvalid) {
        float4 x0 = *(const float4*)(row + j0);
        float4 x1 = *(const float4*)(row + j0 + 4);
        int4 m0 = *(const int4*)(mrow + j0);
        int4 m1 = *(const int4*)(mrow + j0 + 4);
        vals[0] = m0.x ? x0.x : -1e9f; vals[1] = m0.y ? x0.y : -1e9f;
        vals[2] = m0.z ? x0.z : -1e9f; vals[3] = m0.w ? x0.w : -1e9f;
        vals[4] = m1.x ? x1.x : -1e9f; vals[5] = m1.y ? x1.y : -1e9f;
        vals[6] = m1.z ? x1.z : -1e9f; vals[7] = m1.w ? x1.w : -1e9f;
#pragma unroll
        for (int t = 0; t < 8; ++t) vmax = fmaxf(vmax, vals[t]);
    } else {
#pragma unroll
        for (int t = 0; t < 8; ++t) {
            int j = j0 + t;
            float s = -INFINITY;
            if (j < nvalid) {
                s = row[j];
                if (mrow[j] == 0) s = -1e9f;
            }
            vals[t] = s;
            vmax = fmaxf(vmax, s);
        }
    }

    __shared__ float red[8];
#pragma unroll
    for (int o = 16; o; o >>= 1) vmax = fmaxf(vmax, __shfl_xor_sync(~0u, vmax, o));
    if ((tid & 31) == 0) red[tid >> 5] = vmax;
    __syncthreads();
    if (tid < 32) {
        float x = (tid < 8) ? red[tid] : -INFINITY;
#pragma unroll
        for (int o = 4; o; o >>= 1) x = fmaxf(x, __shfl_xor_sync(~0u, x, o));
        if (tid == 0) red[0] = x;
    }
    __syncthreads();
    vmax = red[0];
    __syncthreads();

    float lsum = 0.f;
#pragma unroll
    for (int t = 0; t < 8; ++t) {
        float e = __expf(vals[t] - vmax);
        vals[t] = e;
        lsum += e;
    }
#pragma unroll
    for (int o = 16; o; o >>= 1) lsum += __shfl_xor_sync(~0u, lsum, o);
    if ((tid & 31) == 0) red[tid >> 5] = lsum;
    __syncthreads();
    if (tid < 32) {
        float x = (tid < 8) ? red[tid] : 0.f;
#pragma unroll
        for (int o = 4; o; o >>= 1) x += __shfl_xor_sync(~0u, x, o);
        if (tid == 0) red[0] = x;
    }
    __syncthreads();
    const float rinv = 1.0f / red[0];

    if (j0 < nfill) {
        union { __half h[8]; uint4 u; } P;
#pragma unroll
        for (int t = 0; t < 8; ++t)
            P.h[t] = __float2half_rn(vals[t] * rinv);   // 0 for j > i
        *(uint4*)(Phi + rowoff + j0) = P.u;
    }
}

// ---------------------------------------------------------------------------
extern "C" void kernel_launch(void* const* d_in, const int* in_sizes, int n_in,
                              void* d_out, int out_size)
{
    (void)in_sizes; (void)n_in; (void)out_size;

    const float* q    = (const float*)d_in[0];
    const float* k    = (const float*)d_in[1];
    const float* v    = (const float*)d_in[2];
    const int*   mask = (const int*)  d_in[3];
    const float* Wq   = (const float*)d_in[4];
    const float* bq   = (const float*)d_in[5];
    const float* Wk   = (const float*)d_in[6];
    const float* bk   = (const float*)d_in[7];
    const float* Wv   = (const float*)d_in[8];
    const float* bv   = (const float*)d_in[9];
    float* out = (float*)d_out;

    static bool init = false;
    static __half *Xqh, *Xkh, *Xvh, *Wqh, *Wkh, *Wvh;
    static __half *QHh, *KHh, *VTh, *Ph;
    static float *SC;
    if (!init) {
        void* p;
        cudaGetSymbolAddress(&p, g_Xq_hi); Xqh = (__half*)p;
        cudaGetSymbolAddress(&p, g_Xk_hi); Xkh = (__half*)p;
        cudaGetSymbolAddress(&p, g_Xv_hi); Xvh = (__half*)p;
        cudaGetSymbolAddress(&p, g_Wq_hi); Wqh = (__half*)p;
        cudaGetSymbolAddress(&p, g_Wk_hi); Wkh = (__half*)p;
        cudaGetSymbolAddress(&p, g_Wv_hi); Wvh = (__half*)p;
        cudaGetSymbolAddress(&p, g_QH_hi); QHh = (__half*)p;
        cudaGetSymbolAddress(&p, g_KH_hi); KHh = (__half*)p;
        cudaGetSymbolAddress(&p, g_VT_hi); VTh = (__half*)p;
        cudaGetSymbolAddress(&p, g_P_hi);  Ph  = (__half*)p;
        cudaGetSymbolAddress(&p, g_SC);    SC  = (float*)p;
        cudaFuncSetAttribute((const void*)gemm_proj3, cudaFuncAttributeMaxDynamicSharedMemorySize, SMEMSZ);
        cudaFuncSetAttribute((const void*)gemm_sc,    cudaFuncAttributeMaxDynamicSharedMemorySize, SMEMSZ);
        cudaFuncSetAttribute((const void*)gemm_pv,    cudaFuncAttributeMaxDynamicSharedMemorySize, SMEMSZ);
        init = true;
    }

    // 1) Convert all 6 inputs to fp16 in one launch (4x float4 per thread)
    const size_t nX4 = (size_t)NT * MD / 4;
    const size_t nW4 = (size_t)HD * MD / 4;
    convert_hi6<<<dim3((unsigned)((nX4 / 4 + 255) / 256), 6), 256>>>(
        q, k, v, Wq, Wk, Wv, Xqh, Xkh, Xvh, Wqh, Wkh, Wvh, nX4, nW4);

    // 2) All 3 projections in ONE launch; V writes VT directly
    dim3 gproj(HD / 128, NT / 128, 3);
    gemm_proj3<<<gproj, 256, SMEMSZ>>>(Xqh, Xkh, Xvh, Wqh, Wkh, Wvh,
                                       bq, bk, bv, QHh, KHh, VTh);

    // 3) Scores (1-pass, causal skip at 128x128 granularity)
    dim3 gsc(SS / 128, SS / 128, BB);
    gemm_sc<<<gsc, 256, SMEMSZ>>>(QHh, KHh, SC, 1.0f / 32.0f);

    // 4) Softmax -> P fp16
    softmax_rows<<<dim3(SS, BB), 256>>>(mask, SC, Ph);

    // 5) OUT = P @ VT^T (longest-first CTA order)
    dim3 go(HD / 128, SS / 128, BB);
    gemm_pv<<<go, 256, SMEMSZ>>>(Ph, VTh, out);
}

// round 15
// speedup vs baseline: 2.3284x; 1.0508x over previous
#include <cuda_runtime.h>
#include <cuda_fp16.h>
#include <math.h>
#include <stdint.h>

// Problem dims (fixed)
#define BB 4
#define SS 2048
#define MD 1024
#define HD 1024
#define NT 8192   // BB*SS

// GEMM tiling: CTA 128x128, 8 warps (2x4) of 64x32, K-chunk 64, 1-pass fp16
// occupancy 2 CTAs/SM
#define KC 64
#define STG    32768          // A(16K) + B(16K)
#define NS     3              // pipeline stages
#define SMEMSZ (NS * STG)     // 96 KB -> 2 CTAs/SM

#define SWZ(o) ((o) ^ (((o) >> 3) & 0x70))

// ---------------------------------------------------------------------------
// Scratch (__device__ globals; allocation-free rule)
// ---------------------------------------------------------------------------
__device__ __align__(256) __half g_Xq_hi[(size_t)NT * MD];
__device__ __align__(256) __half g_Xk_hi[(size_t)NT * MD];
__device__ __align__(256) __half g_Xv_hi[(size_t)NT * MD];
__device__ __align__(256) __half g_Wq_hi[(size_t)HD * MD];
__device__ __align__(256) __half g_Wk_hi[(size_t)HD * MD];
__device__ __align__(256) __half g_Wv_hi[(size_t)HD * MD];
__device__ __align__(256) __half g_QH_hi[(size_t)NT * HD];
__device__ __align__(256) __half g_KH_hi[(size_t)NT * HD];
__device__ __align__(256) __half g_VT_hi[(size_t)BB * HD * SS];
__device__ __align__(256) __half g_SC[(size_t)BB * SS * SS];     // fp16 scores
__device__ __align__(256) __half g_P_hi[(size_t)BB * SS * SS];

// ---------------------------------------------------------------------------
__device__ __forceinline__ uint32_t smem_u32(const void* p) {
    uint32_t a;
    asm("{ .reg .u64 t; cvta.to.shared.u64 t, %1; cvt.u32.u64 %0, t; }"
        : "=r"(a) : "l"(p));
    return a;
}
#define CP16(dst, src) asm volatile("cp.async.cg.shared.global [%0], [%1], 16;" :: "r"(dst), "l"(src))
#define CP_COMMIT()    asm volatile("cp.async.commit_group;" ::: "memory")
#define CP_WAIT1()     asm volatile("cp.async.wait_group 1;" ::: "memory")

__device__ __forceinline__ void ldsm4(uint32_t r[4], uint32_t a) {
    asm volatile("ldmatrix.sync.aligned.m8n8.x4.shared.b16 {%0,%1,%2,%3}, [%4];"
                 : "=r"(r[0]), "=r"(r[1]), "=r"(r[2]), "=r"(r[3]) : "r"(a));
}
__device__ __forceinline__ void mma_f32(float d[4], const uint32_t a[4],
                                        uint32_t b0, uint32_t b1) {
    asm volatile(
        "mma.sync.aligned.m16n8k16.row.col.f32.f16.f16.f32 "
        "{%0,%1,%2,%3}, {%4,%5,%6,%7}, {%8,%9}, {%0,%1,%2,%3};"
        : "+f"(d[0]), "+f"(d[1]), "+f"(d[2]), "+f"(d[3])
        : "r"(a[0]), "r"(a[1]), "r"(a[2]), "r"(a[3]), "r"(b0), "r"(b1));
}

__device__ __forceinline__ uint32_t pack_h2(__half a, __half b) {
    union { __half2 v; uint32_t u; } t;
    t.v.x = a; t.v.y = b;
    return t.u;
}

// ---------------------------------------------------------------------------
// GEMM mainloop (1-pass fp16 NT), CTA tile 128x128, warp tile 64x32.
// ---------------------------------------------------------------------------
struct GemmCtx {
    const char* gA;
    const char* gB;
    size_t ldaB, ldbB;
};

__device__ __forceinline__ void gemm_mainloop(
    const GemmCtx& cx, uint32_t sb, int tid, int lane, int wm, int wn,
    int nkt, float acc[4][4][4])
{
    auto load_chunk = [&](int c, int buf) {
        const uint32_t st = sb + buf * STG;
        const size_t cb = (size_t)c * 128;
#pragma unroll
        for (int i = 0; i < 4; ++i) {          // A: 128 rows x 128B
            const int idx = tid + i * 256;
            const int row = idx >> 3, seg = (idx & 7) * 16;
            CP16(st + SWZ(row * 128 + seg), cx.gA + (size_t)row * cx.ldaB + cb + seg);
        }
#pragma unroll
        for (int i = 0; i < 4; ++i) {          // B: 128 rows x 128B
            const int idx = tid + i * 256;
            const int row = idx >> 3, seg = (idx & 7) * 16;
            CP16(st + 16384 + SWZ(row * 128 + seg), cx.gB + (size_t)row * cx.ldbB + cb + seg);
        }
        CP_COMMIT();
    };

    const int lrow = lane & 15;
    const int lcb0 = (lane >> 4) * 16;
    const int arow = wm * 64 + lrow;
    const int brow = wn * 32 + lrow;

#pragma unroll
    for (int i = 0; i < NS - 1; ++i)
        if (i < nkt) load_chunk(i, i);
        else         CP_COMMIT();

    for (int c = 0; c < nkt; ++c) {
        CP_WAIT1();
        __syncthreads();
        if (c + NS - 1 < nkt) load_chunk(c + NS - 1, (c + NS - 1) % NS);
        else                  CP_COMMIT();   // keep wait-group count aligned

        const uint32_t st = sb + (c % NS) * STG;
#pragma unroll
        for (int kk = 0; kk < 4; ++kk) {
            const int cb = kk * 32 + lcb0;
            uint32_t a[4][4], bh[2][4];
#pragma unroll
            for (int mi = 0; mi < 4; ++mi)
                ldsm4(a[mi], st + SWZ((arow + mi * 16) * 128 + cb));
#pragma unroll
            for (int nj = 0; nj < 2; ++nj)
                ldsm4(bh[nj], st + 16384 + SWZ((brow + nj * 16) * 128 + cb));
#pragma unroll
            for (int mi = 0; mi < 4; ++mi)
#pragma unroll
                for (int nj = 0; nj < 2; ++nj) {
                    mma_f32(acc[mi][nj * 2 + 0], a[mi], bh[nj][0], bh[nj][2]);
                    mma_f32(acc[mi][nj * 2 + 1], a[mi], bh[nj][1], bh[nj][3]);
                }
        }
    }
}

// ---------------------------------------------------------------------------
// Q/K projections: grid.z in {0,1} selects q/k. Row-major fp16 out + bias.
// ---------------------------------------------------------------------------
__global__ void __launch_bounds__(256, 2)
gemm_proj_qk(const __half* __restrict__ A0, const __half* __restrict__ A1,
             const __half* __restrict__ B0, const __half* __restrict__ B1,
             const float* __restrict__ b0p, const float* __restrict__ b1p,
             __half* __restrict__ C0, __half* __restrict__ C1)
{
    const int bm = blockIdx.y, bn = blockIdx.x, t = blockIdx.z;
    const __half* A   = (t == 0) ? A0 : A1;
    const __half* B   = (t == 0) ? B0 : B1;
    const float* bias = (t == 0) ? b0p : b1p;
    __half* Ch        = (t == 0) ? C0 : C1;

    extern __shared__ char smem[];
    const uint32_t sb = smem_u32(smem);
    const int tid = threadIdx.x, lane = tid & 31, wid = tid >> 5;
    const int wm = wid >> 2, wn = wid & 3;

    GemmCtx cx;
    cx.gA = (const char*)(A + (size_t)(bm * 128) * MD);
    cx.gB = (const char*)(B + (size_t)(bn * 128) * MD);
    cx.ldaB = (size_t)MD * 2;
    cx.ldbB = (size_t)MD * 2;

    float acc[4][4][4];
#pragma unroll
    for (int mi = 0; mi < 4; ++mi)
#pragma unroll
        for (int nf = 0; nf < 4; ++nf)
#pragma unroll
            for (int r = 0; r < 4; ++r) acc[mi][nf][r] = 0.f;

    gemm_mainloop(cx, sb, tid, lane, wm, wn, MD / KC, acc);

    const int lr = lane >> 2;
    const int lc = (lane & 3) * 2;
#pragma unroll
    for (int mi = 0; mi < 4; ++mi) {
        const int row0 = bm * 128 + wm * 64 + mi * 16 + lr;
#pragma unroll
        for (int nf = 0; nf < 4; ++nf) {
            const int col = bn * 128 + wn * 32 + nf * 8 + lc;
            float* d = acc[mi][nf];
            const float bb0 = bias[col], bb1 = bias[col + 1];
            *(uint32_t*)(Ch + (size_t)row0 * HD + col) =
                pack_h2(__float2half_rn(d[0] + bb0), __float2half_rn(d[1] + bb1));
            *(uint32_t*)(Ch + (size_t)(row0 + 8) * HD + col) =
                pack_h2(__float2half_rn(d[2] + bb0), __float2half_rn(d[3] + bb1));
        }
    }
}

// ---------------------------------------------------------------------------
// Merged launch: z<4 -> scores batch z (causal skip, fp16 out * alpha);
//                z==4 -> V projection writing VT[b][h][s] directly.
// Grid (16, 32, 5). Scores: bm=y (<16), bn=x (<=bm). V: idx=y*16+x -> 512 CTAs.
// ---------------------------------------------------------------------------
__global__ void __launch_bounds__(256, 2)
gemm_sc_vp(const __half* __restrict__ QH, const __half* __restrict__ KH,
           __half* __restrict__ SCh, float alpha,
           const __half* __restrict__ Xv, const __half* __restrict__ Wv,
           const float* __restrict__ bv, __half* __restrict__ VT)
{
    const int z = blockIdx.z;
    extern __shared__ char smem[];
    const uint32_t sb = smem_u32(smem);
    const int tid = threadIdx.x, lane = tid & 31, wid = tid >> 5;
    const int wm = wid >> 2, wn = wid & 3;
    const int lr = lane >> 2;
    const int lc = (lane & 3) * 2;

    if (z < 4) {
        const int bm = blockIdx.y, bn = blockIdx.x;
        if (bm >= 16 || bn > bm) return;

        GemmCtx cx;
        cx.gA = (const char*)(QH + (size_t)z * SS * HD + (size_t)(bm * 128) * HD);
        cx.gB = (const char*)(KH + (size_t)z * SS * HD + (size_t)(bn * 128) * HD);
        cx.ldaB = (size_t)HD * 2;
        cx.ldbB = (size_t)HD * 2;

        float acc[4][4][4];
#pragma unroll
        for (int mi = 0; mi < 4; ++mi)
#pragma unroll
            for (int nf = 0; nf < 4; ++nf)
#pragma unroll
                for (int r = 0; r < 4; ++r) acc[mi][nf][r] = 0.f;

        gemm_mainloop(cx, sb, tid, lane, wm, wn, HD / KC, acc);

        __half* cp = SCh + (size_t)z * SS * SS;
#pragma unroll
        for (int mi = 0; mi < 4; ++mi) {
            const int row0 = bm * 128 + wm * 64 + mi * 16 + lr;
#pragma unroll
            for (int nf = 0; nf < 4; ++nf) {
                const int col = bn * 128 + wn * 32 + nf * 8 + lc;
                float* d = acc[mi][nf];
                *(uint32_t*)(cp + (size_t)row0 * SS + col) =
                    pack_h2(__float2half_rn(d[0] * alpha), __float2half_rn(d[1] * alpha));
                *(uint32_t*)(cp + (size_t)(row0 + 8) * SS + col) =
                    pack_h2(__float2half_rn(d[2] * alpha), __float2half_rn(d[3] * alpha));
            }
        }
    } else {
        const int idx = blockIdx.y * 16 + blockIdx.x;   // 0..511
        const int bn = idx & 7;     // HD/128 = 8
        const int bm = idx >> 3;    // NT/128 = 64

        GemmCtx cx;
        cx.gA = (const char*)(Xv + (size_t)(bm * 128) * MD);
        cx.gB = (const char*)(Wv + (size_t)(bn * 128) * MD);
        cx.ldaB = (size_t)MD * 2;
        cx.ldbB = (size_t)MD * 2;

        float acc[4][4][4];
#pragma unroll
        for (int mi = 0; mi < 4; ++mi)
#pragma unroll
            for (int nf = 0; nf < 4; ++nf)
#pragma unroll
                for (int r = 0; r < 4; ++r) acc[mi][nf][r] = 0.f;

        gemm_mainloop(cx, sb, tid, lane, wm, wn, MD / KC, acc);

        // transpose tile through smem -> VT[b][h][s] coalesced
        __syncthreads();   // pipeline smem no longer in use
        constexpr int TP = 136;                 // padded row (halfs)
        __half* ts = (__half*)smem;             // [128][TP] = 34816 B
#pragma unroll
        for (int mi = 0; mi < 4; ++mi) {
            const int sl0 = wm * 64 + mi * 16 + lr;
#pragma unroll
            for (int nf = 0; nf < 4; ++nf) {
                const int hl = wn * 32 + nf * 8 + lc;
                float* d = acc[mi][nf];
                const float bb0 = bv[bn * 128 + hl], bb1 = bv[bn * 128 + hl + 1];
                ts[(hl + 0) * TP + sl0]     = __float2half_rn(d[0] + bb0);
                ts[(hl + 1) * TP + sl0]     = __float2half_rn(d[1] + bb1);
                ts[(hl + 0) * TP + sl0 + 8] = __float2half_rn(d[2] + bb0);
                ts[(hl + 1) * TP + sl0 + 8] = __float2half_rn(d[3] + bb1);
            }
        }
        __syncthreads();
        const int grow = bm * 128;
        const int b    = grow >> 11;            // SS = 2048
        const int s0   = grow & 2047;
        __half* dst = VT + (size_t)b * HD * SS + s0;
#pragma unroll
        for (int it = 0; it < 8; ++it) {        // 2048 uint4 units
            const int i2 = tid + it * 256;
            const int hl = i2 >> 4, seg = (i2 & 15) * 8;
            *(uint4*)(dst + (size_t)(bn * 128 + hl) * SS + seg) =
                *(const uint4*)&ts[hl * TP + seg];
        }
    }
}

// ---------------------------------------------------------------------------
// PV GEMM: OUT = P @ VT^T, k-chunks limited by causality, longest-first.
// ---------------------------------------------------------------------------
__global__ void __launch_bounds__(256, 2)
gemm_pv(const __half* __restrict__ A, const __half* __restrict__ B,
        float* __restrict__ Cf)
{
    const int bm = (int)gridDim.y - 1 - blockIdx.y;   // longest first
    const int bn = blockIdx.x, bz = blockIdx.z;
    const int nkt = (bm + 1) * 2;

    extern __shared__ char smem[];
    const uint32_t sb = smem_u32(smem);
    const int tid = threadIdx.x, lane = tid & 31, wid = tid >> 5;
    const int wm = wid >> 2, wn = wid & 3;

    GemmCtx cx;
    cx.gA = (const char*)(A + (size_t)bz * SS * SS + (size_t)(bm * 128) * SS);
    cx.gB = (const char*)(B + (size_t)bz * HD * SS + (size_t)(bn * 128) * SS);
    cx.ldaB = (size_t)SS * 2;
    cx.ldbB = (size_t)SS * 2;

    float acc[4][4][4];
#pragma unroll
    for (int mi = 0; mi < 4; ++mi)
#pragma unroll
        for (int nf = 0; nf < 4; ++nf)
#pragma unroll
            for (int r = 0; r < 4; ++r) acc[mi][nf][r] = 0.f;

    gemm_mainloop(cx, sb, tid, lane, wm, wn, nkt, acc);

    const int lr = lane >> 2;
    const int lc = (lane & 3) * 2;
    float* cp = Cf + (size_t)bz * SS * HD;
#pragma unroll
    for (int mi = 0; mi < 4; ++mi) {
        const int row0 = bm * 128 + wm * 64 + mi * 16 + lr;
#pragma unroll
        for (int nf = 0; nf < 4; ++nf) {
            const int col = bn * 128 + wn * 32 + nf * 8 + lc;
            float* d = acc[mi][nf];
            float2 o0 = { d[0], d[1] };
            float2 o1 = { d[2], d[3] };
            *(float2*)(cp + (size_t)row0 * HD + col) = o0;
            *(float2*)(cp + (size_t)(row0 + 8) * HD + col) = o1;
        }
    }
}

// ---------------------------------------------------------------------------
// Fused convert: 6 tensors -> fp16, 4x float4 per thread (MLP=4).
// ---------------------------------------------------------------------------
__global__ void __launch_bounds__(256)
convert_hi6(const float* __restrict__ s0, const float* __restrict__ s1,
            const float* __restrict__ s2, const float* __restrict__ s3,
            const float* __restrict__ s4, const float* __restrict__ s5,
            __half* __restrict__ h0, __half* __restrict__ h1,
            __half* __restrict__ h2, __half* __restrict__ h3,
            __half* __restrict__ h4, __half* __restrict__ h5,
            size_t nX4, size_t nW4)
{
    const int t = blockIdx.y;
    const size_t n4 = (t < 3) ? nX4 : nW4;
    const size_t i0 = ((size_t)blockIdx.x * blockDim.x + threadIdx.x) * 4;
    if (i0 >= n4) return;   // n4 is a multiple of 4
    const float* src = (t == 0) ? s0 : (t == 1) ? s1 : (t == 2) ? s2
                     : (t == 3) ? s3 : (t == 4) ? s4 : s5;
    __half* hi = (t == 0) ? h0 : (t == 1) ? h1 : (t == 2) ? h2
               : (t == 3) ? h3 : (t == 4) ? h4 : h5;
    float4 x[4];
#pragma unroll
    for (int u = 0; u < 4; ++u) x[u] = ((const float4*)src)[i0 + u];
#pragma unroll
    for (int u = 0; u < 4; ++u) {
        union { __half h[4]; uint2 v; } H;
        H.h[0] = __float2half_rn(x[u].x);
        H.h[1] = __float2half_rn(x[u].y);
        H.h[2] = __float2half_rn(x[u].z);
        H.h[3] = __float2half_rn(x[u].w);
        ((uint2*)hi)[i0 + u] = H.v;
    }
}

// ---------------------------------------------------------------------------
// Masked causal softmax: SC fp16 -> P fp16, zero-filled to 128-boundary.
// ---------------------------------------------------------------------------
__global__ void __launch_bounds__(256)
softmax_rows(const int* __restrict__ mask, const __half* __restrict__ SC,
             __half* __restrict__ Phi)
{
    const int b = blockIdx.y;
    const int i = blockIdx.x;
    const size_t rowoff = ((size_t)b * SS + i) * SS;
    const __half* row = SC + rowoff;
    const int* mrow = mask + (size_t)b * SS;
    const int tid = threadIdx.x;
    const int nvalid = i + 1;
    const int nfill = ((i >> 7) + 1) << 7;
    const int j0 = tid * 8;

    float vals[8];
    float vmax = -INFINITY;
    if (j0 + 7 < nvalid) {
        uint4 r8 = *(const uint4*)(row + j0);   // 8 halfs
        const __half2* hp = (const __half2*)&r8;
        float2 f0 = __half22float2(hp[0]);
        float2 f1 = __half22float2(hp[1]);
        float2 f2 = __half22float2(hp[2]);
        float2 f3 = __half22float2(hp[3]);
        int4 m0 = *(const int4*)(mrow + j0);
        int4 m1 = *(const int4*)(mrow + j0 + 4);
        vals[0] = m0.x ? f0.x : -1e9f; vals[1] = m0.y ? f0.y : -1e9f;
        vals[2] = m0.z ? f1.x : -1e9f; vals[3] = m0.w ? f1.y : -1e9f;
        vals[4] = m1.x ? f2.x : -1e9f; vals[5] = m1.y ? f2.y : -1e9f;
        vals[6] = m1.z ? f3.x : -1e9f; vals[7] = m1.w ? f3.y : -1e9f;
#pragma unroll
        for (int t = 0; t < 8; ++t) vmax = fmaxf(vmax, vals[t]);
    } else {
#pragma unroll
        for (int t = 0; t < 8; ++t) {
            int j = j0 + t;
            float s = -INFINITY;
            if (j < nvalid) {
                s = __half2float(row[j]);
                if (mrow[j] == 0) s = -1e9f;
            }
            vals[t] = s;
            vmax = fmaxf(vmax, s);
        }
    }

    __shared__ float red[8];
#pragma unroll
    for (int o = 16; o; o >>= 1) vmax = fmaxf(vmax, __shfl_xor_sync(~0u, vmax, o));
    if ((tid & 31) == 0) red[tid >> 5] = vmax;
    __syncthreads();
    if (tid < 32) {
        float x = (tid < 8) ? red[tid] : -INFINITY;
#pragma unroll
        for (int o = 4; o; o >>= 1) x = fmaxf(x, __shfl_xor_sync(~0u, x, o));
        if (tid == 0) red[0] = x;
    }
    __syncthreads();
    vmax = red[0];
    __syncthreads();

    float lsum = 0.f;
#pragma unroll
    for (int t = 0; t < 8; ++t) {
        float e = __expf(vals[t] - vmax);
        vals[t] = e;
        lsum += e;
    }
#pragma unroll
    for (int o = 16; o; o >>= 1) lsum += __shfl_xor_sync(~0u, lsum, o);
    if ((tid & 31) == 0) red[tid >> 5] = lsum;
    __syncthreads();
    if (tid < 32) {
        float x = (tid < 8) ? red[tid] : 0.f;
#pragma unroll
        for (int o = 4; o; o >>= 1) x += __shfl_xor_sync(~0u, x, o);
        if (tid == 0) red[0] = x;
    }
    __syncthreads();
    const float rinv = 1.0f / red[0];

    if (j0 < nfill) {
        union { __half h[8]; uint4 u; } P;
#pragma unroll
        for (int t = 0; t < 8; ++t)
            P.h[t] = __float2half_rn(vals[t] * rinv);   // 0 for j > i
        *(uint4*)(Phi + rowoff + j0) = P.u;
    }
}

// ---------------------------------------------------------------------------
extern "C" void kernel_launch(void* const* d_in, const int* in_sizes, int n_in,
                              void* d_out, int out_size)
{
    (void)in_sizes; (void)n_in; (void)out_size;

    const float* q    = (const float*)d_in[0];
    const float* k    = (const float*)d_in[1];
    const float* v    = (const float*)d_in[2];
    const int*   mask = (const int*)  d_in[3];
    const float* Wq   = (const float*)d_in[4];
    const float* bq   = (const float*)d_in[5];
    const float* Wk   = (const float*)d_in[6];
    const float* bk   = (const float*)d_in[7];
    const float* Wv   = (const float*)d_in[8];
    const float* bv   = (const float*)d_in[9];
    float* out = (float*)d_out;

    static bool init = false;
    static __half *Xqh, *Xkh, *Xvh, *Wqh, *Wkh, *Wvh;
    static __half *QHh, *KHh, *VTh, *Ph, *SC;
    if (!init) {
        void* p;
        cudaGetSymbolAddress(&p, g_Xq_hi); Xqh = (__half*)p;
        cudaGetSymbolAddress(&p, g_Xk_hi); Xkh = (__half*)p;
        cudaGetSymbolAddress(&p, g_Xv_hi); Xvh = (__half*)p;
        cudaGetSymbolAddress(&p, g_Wq_hi); Wqh = (__half*)p;
        cudaGetSymbolAddress(&p, g_Wk_hi); Wkh = (__half*)p;
        cudaGetSymbolAddress(&p, g_Wv_hi); Wvh = (__half*)p;
        cudaGetSymbolAddress(&p, g_QH_hi); QHh = (__half*)p;
        cudaGetSymbolAddress(&p, g_KH_hi); KHh = (__half*)p;
        cudaGetSymbolAddress(&p, g_VT_hi); VTh = (__half*)p;
        cudaGetSymbolAddress(&p, g_P_hi);  Ph  = (__half*)p;
        cudaGetSymbolAddress(&p, g_SC);    SC  = (__half*)p;
        cudaFuncSetAttribute((const void*)gemm_proj_qk, cudaFuncAttributeMaxDynamicSharedMemorySize, SMEMSZ);
        cudaFuncSetAttribute((const void*)gemm_sc_vp,   cudaFuncAttributeMaxDynamicSharedMemorySize, SMEMSZ);
        cudaFuncSetAttribute((const void*)gemm_pv,      cudaFuncAttributeMaxDynamicSharedMemorySize, SMEMSZ);
        init = true;
    }

    // 1) Convert all 6 inputs to fp16 in one launch (4x float4 per thread)
    const size_t nX4 = (size_t)NT * MD / 4;
    const size_t nW4 = (size_t)HD * MD / 4;
    convert_hi6<<<dim3((unsigned)((nX4 / 4 + 255) / 256), 6), 256>>>(
        q, k, v, Wq, Wk, Wv, Xqh, Xkh, Xvh, Wqh, Wkh, Wvh, nX4, nW4);

    // 2) Q/K projections in one launch
    dim3 gqk(HD / 128, NT / 128, 2);
    gemm_proj_qk<<<gqk, 256, SMEMSZ>>>(Xqh, Xkh, Wqh, Wkh, bq, bk, QHh, KHh);

    // 3) Merged: scores (z<4, causal skip) + V projection (z=4) -> fills wave tail
    dim3 gsv(16, 32, 5);
    gemm_sc_vp<<<gsv, 256, SMEMSZ>>>(QHh, KHh, SC, 1.0f / 32.0f,
                                     Xvh, Wvh, bv, VTh);

    // 4) Softmax (fp16 scores) -> P fp16
    softmax_rows<<<dim3(SS, BB), 256>>>(mask, SC, Ph);

    // 5) OUT = P @ VT^T (longest-first CTA order)
    dim3 go(HD / 128, SS / 128, BB);
    gemm_pv<<<go, 256, SMEMSZ>>>(Ph, VTh, out);
}